// round 11
// baseline (speedup 1.0000x reference)
#include <cuda_runtime.h>
#include <cuda_bf16.h>
#include <cstdint>

#define Bb 4
#define Nn 4096
#define Dd 256
#define Mm (Bb*Nn)

__device__ __nv_bfloat16 g_xhi[Mm*Dd], g_xlo[Mm*Dd];
__device__ __nv_bfloat16 g_Whi[3*Dd*Dd], g_Wlo[3*Dd*Dd];
__device__ __nv_bfloat16 g_Qhi[Mm*Dd], g_Qlo[Mm*Dd];
__device__ __nv_bfloat16 g_Khi[Mm*Dd], g_Klo[Mm*Dd];
__device__ __nv_bfloat16 g_Vhi[Mm*Dd], g_Vlo[Mm*Dd];

// ---------------- mma.sync / ldmatrix / cp.async ----------------
__device__ __forceinline__ uint32_t smem_u32(const void* p)
{ uint32_t a;
  asm("{ .reg .u64 t; cvta.to.shared.u64 t, %1; cvt.u32.u64 %0, t; }":"=r"(a):"l"(p));
  return a; }

__device__ __forceinline__ void ldsm4(uint32_t* r, uint32_t a)
{ asm volatile("ldmatrix.sync.aligned.m8n8.x4.shared.b16 {%0,%1,%2,%3}, [%4];"
    : "=r"(r[0]), "=r"(r[1]), "=r"(r[2]), "=r"(r[3]) : "r"(a)); }
__device__ __forceinline__ void ldsm4t(uint32_t* r, uint32_t a)
{ asm volatile("ldmatrix.sync.aligned.m8n8.x4.trans.shared.b16 {%0,%1,%2,%3}, [%4];"
    : "=r"(r[0]), "=r"(r[1]), "=r"(r[2]), "=r"(r[3]) : "r"(a)); }

__device__ __forceinline__ void mma16816(float* c, const uint32_t* a, const uint32_t* b)
{ asm volatile("mma.sync.aligned.m16n8k16.row.col.f32.bf16.bf16.f32 "
    "{%0,%1,%2,%3}, {%4,%5,%6,%7}, {%8,%9}, {%0,%1,%2,%3};"
    : "+f"(c[0]), "+f"(c[1]), "+f"(c[2]), "+f"(c[3])
    : "r"(a[0]), "r"(a[1]), "r"(a[2]), "r"(a[3]), "r"(b[0]), "r"(b[1])); }

#define CPA16(d, s) asm volatile("cp.async.cg.shared.global [%0], [%1], 16;"::"r"(d),"l"(s))
#define CPCOMMIT()  asm volatile("cp.async.commit_group;":::"memory")
#define CPWAIT0()   asm volatile("cp.async.wait_group 0;":::"memory")

// swizzled blocked-atom layouts (Swizzle<3,4,3>, 128B rows)
#define SWZ(o) ((o) ^ (((o) >> 3) & 0x70))
__device__ __forceinline__ uint32_t xswz(int r, int cb)   // 128 rows x 512B
{ return SWZ((uint32_t)((((r>>3) + (cb>>7)*16)*1024) + (r&7)*128 + (cb&127))); }
__device__ __forceinline__ uint32_t qswz(int r, int cb)   // 64 rows x 512B
{ return SWZ((uint32_t)((((r>>3) + (cb>>7)*8)*1024) + (r&7)*128 + (cb&127))); }
__device__ __forceinline__ uint32_t kswz(int r, int cb)   // 32 rows x 512B
{ return SWZ((uint32_t)((((r>>3) + (cb>>7)*4)*1024) + (r&7)*128 + (cb&127))); }
__device__ __forceinline__ uint32_t pswz(int r, int cb)   // 128B rows
{ return SWZ((uint32_t)(r*128 + cb)); }

// attention SMEM map
#define SM_QH 0
#define SM_QL 32768
#define SM_K  65536    // 2 stages x 32KB (Kh 16K | Kl 16K)
#define SM_V  131072   // 2 stages x 32KB (Vh 16K | Vl 16K)
#define SM_P  196608   // 2 x 8KB
#define SM_TOT 212992

// qkvmm SMEM map
#define SMX_H 0
#define SMX_L 65536
#define SMW_H 131072
#define SMW_L 163840
#define SM_QKV_TOT 196608

// ---------------------------------------------------------------------------
// convX / convW: fp32 -> bf16 hi/lo splits
// ---------------------------------------------------------------------------
__global__ __launch_bounds__(256, 4) void convX_kernel(const float* __restrict__ x)
{
    size_t i = (size_t)(blockIdx.x * 256 + threadIdx.x) * 4;
    float4 v = *(const float4*)&x[i];
    float a[4] = {v.x, v.y, v.z, v.w};
    ushort h[4], l[4];
    #pragma unroll
    for (int k = 0; k < 4; k++) {
        __nv_bfloat16 hb = __float2bfloat16(a[k]);
        h[k] = __bfloat16_as_ushort(hb);
        l[k] = __bfloat16_as_ushort(__float2bfloat16(a[k] - __bfloat162float(hb)));
    }
    *(uint2*)&g_xhi[i] = make_uint2(h[0] | ((uint32_t)h[1]<<16), h[2] | ((uint32_t)h[3]<<16));
    *(uint2*)&g_xlo[i] = make_uint2(l[0] | ((uint32_t)l[1]<<16), l[2] | ((uint32_t)l[3]<<16));
}

__global__ __launch_bounds__(256, 4)
void convW_kernel(const float* __restrict__ Wq, const float* __restrict__ Wk,
                  const float* __restrict__ Wv)
{
    const int z = blockIdx.y;
    const float* in = (z == 0) ? Wq : (z == 1) ? Wk : Wv;
    size_t base = (size_t)z * Dd * Dd;
    size_t i = (size_t)(blockIdx.x * 256 + threadIdx.x) * 4;
    float4 v = *(const float4*)&in[i];
    float a[4] = {v.x, v.y, v.z, v.w};
    ushort h[4], l[4];
    #pragma unroll
    for (int k = 0; k < 4; k++) {
        __nv_bfloat16 hb = __float2bfloat16(a[k]);
        h[k] = __bfloat16_as_ushort(hb);
        l[k] = __bfloat16_as_ushort(__float2bfloat16(a[k] - __bfloat162float(hb)));
    }
    *(uint2*)&g_Whi[base + i] = make_uint2(h[0] | ((uint32_t)h[1]<<16), h[2] | ((uint32_t)h[3]<<16));
    *(uint2*)&g_Wlo[base + i] = make_uint2(l[0] | ((uint32_t)l[1]<<16), l[2] | ((uint32_t)l[3]<<16));
}

// ---------------------------------------------------------------------------
// qkvmm: HMMA QKV projection (unchanged — known good)
// ---------------------------------------------------------------------------
__global__ __launch_bounds__(256, 1)
void qkvmm_kernel(const float* __restrict__ bq, const float* __restrict__ bk,
                  const float* __restrict__ bv)
{
    extern __shared__ char sm[];
    uint32_t sb = smem_u32(sm);
    const int t = threadIdx.x, lane = t & 31, wid = t >> 5;
    const int z = blockIdx.x;
    const int m0 = blockIdx.y * 128;
    const float* bias = (z == 0) ? bq : (z == 1) ? bk : bv;
    __nv_bfloat16* ohi = (z == 0) ? g_Qhi : (z == 1) ? g_Khi : g_Vhi;
    __nv_bfloat16* olo = (z == 0) ? g_Qlo : (z == 1) ? g_Klo : g_Vlo;
    const char* xh = (const char*)g_xhi + (size_t)m0 * 512;
    const char* xl = (const char*)g_xlo + (size_t)m0 * 512;
    const char* wh = (const char*)g_Whi + (size_t)z * 131072;
    const char* wl = (const char*)g_Wlo + (size_t)z * 131072;

    #pragma unroll
    for (int i = 0; i < 16; i++) {
        int id = i*256 + t;
        int row = id >> 5, cb = (id & 31) * 16;
        uint32_t o = xswz(row, cb);
        *(uint4*)(sm + SMX_H + o) = *(const uint4*)(xh + (size_t)row*512 + cb);
        *(uint4*)(sm + SMX_L + o) = *(const uint4*)(xl + (size_t)row*512 + cb);
    }

    const int lrow = lane & 15, lk16 = (lane >> 4) * 16;
    const int wrow = (lane >> 4) * 8 + (lane & 7);
    const int kb16 = ((lane >> 3) & 1) * 16;
    const int g = lane >> 2, tq = lane & 3;

    for (int et = 0; et < 4; et++) {
        __syncthreads();
        const char* wph = wh + (size_t)et * 64 * 512;
        const char* wpl = wl + (size_t)et * 64 * 512;
        #pragma unroll
        for (int i = 0; i < 8; i++) {
            int id = i*256 + t;
            int row = id >> 5, cb = (id & 31) * 16;
            uint32_t o = qswz(row, cb);
            *(uint4*)(sm + SMW_H + o) = *(const uint4*)(wph + (size_t)row*512 + cb);
            *(uint4*)(sm + SMW_L + o) = *(const uint4*)(wpl + (size_t)row*512 + cb);
        }
        __syncthreads();

        float acc[8][4] = {};
        #pragma unroll
        for (int ks = 0; ks < 16; ks++) {
            uint32_t axh[4], axl[4];
            uint32_t xo = xswz(16*wid + lrow, ks*32 + lk16);
            ldsm4(axh, sb + SMX_H + xo);
            ldsm4(axl, sb + SMX_L + xo);
            #pragma unroll
            for (int n16 = 0; n16 < 4; n16++) {
                uint32_t bwh[4], bwl[4];
                uint32_t wo = qswz(n16*16 + wrow, ks*32 + kb16);
                ldsm4(bwh, sb + SMW_H + wo);
                ldsm4(bwl, sb + SMW_L + wo);
                mma16816(acc[n16*2],   axh, bwh);
                mma16816(acc[n16*2],   axh, bwl);
                mma16816(acc[n16*2],   axl, bwh);
                mma16816(acc[n16*2+1], axh, bwh + 2);
                mma16816(acc[n16*2+1], axh, bwl + 2);
                mma16816(acc[n16*2+1], axl, bwh + 2);
            }
        }

        size_t row0 = (size_t)(m0 + 16*wid + g);
        #pragma unroll
        for (int n2 = 0; n2 < 8; n2++) {
            int col = et*64 + n2*8 + 2*tq;
            float b0 = bias[col], b1 = bias[col + 1];
            float v00 = acc[n2][0] + b0, v01 = acc[n2][1] + b1;
            float v10 = acc[n2][2] + b0, v11 = acc[n2][3] + b1;
            __nv_bfloat16 h00 = __float2bfloat16(v00), h01 = __float2bfloat16(v01);
            __nv_bfloat16 h10 = __float2bfloat16(v10), h11 = __float2bfloat16(v11);
            uint32_t hw0 = __bfloat16_as_ushort(h00) | ((uint32_t)__bfloat16_as_ushort(h01) << 16);
            uint32_t hw1 = __bfloat16_as_ushort(h10) | ((uint32_t)__bfloat16_as_ushort(h11) << 16);
            ushort l00 = __bfloat16_as_ushort(__float2bfloat16(v00 - __bfloat162float(h00)));
            ushort l01 = __bfloat16_as_ushort(__float2bfloat16(v01 - __bfloat162float(h01)));
            ushort l10 = __bfloat16_as_ushort(__float2bfloat16(v10 - __bfloat162float(h10)));
            ushort l11 = __bfloat16_as_ushort(__float2bfloat16(v11 - __bfloat162float(h11)));
            uint32_t lw0 = l00 | ((uint32_t)l01 << 16);
            uint32_t lw1 = l10 | ((uint32_t)l11 << 16);
            *(uint32_t*)&ohi[row0*Dd + col]       = hw0;
            *(uint32_t*)&olo[row0*Dd + col]       = lw0;
            *(uint32_t*)&ohi[(row0 + 8)*Dd + col] = hw1;
            *(uint32_t*)&olo[(row0 + 8)*Dd + col] = lw1;
        }
    }
}

// ---------------------------------------------------------------------------
// Warp-specialized HMMA flash attention v2: 512 thr / 16 warps.
// Warps 0-7: S (4 row x 2 key-half). Warps 8-15: PV (4 row x 2 col-half).
// PV accum = 64 regs/thread -> no spills. 1 sync/tile.
// ---------------------------------------------------------------------------
__global__ __launch_bounds__(512, 1)
void attn_kernel(const int* __restrict__ mask, float* __restrict__ out)
{
    extern __shared__ char sm[];
    uint32_t sb = smem_u32(sm);
    const int t = threadIdx.x, lane = t & 31, wid = t >> 5;
    const int b = blockIdx.y, q0 = blockIdx.x * 64;
    const int g = lane >> 2, tq = lane & 3;
    const int lrow = lane & 15, lk16 = (lane >> 4) * 16;

    // Q hi/lo -> smem (blocked swizzled): 2048 chunks each
    {
        const char* qh = (const char*)&g_Qhi[(size_t)(b*Nn + q0)*Dd];
        const char* ql = (const char*)&g_Qlo[(size_t)(b*Nn + q0)*Dd];
        #pragma unroll
        for (int i = 0; i < 4; i++) {
            int id = i*512 + t;
            int row = id >> 5, cb = (id & 31) * 16;
            uint32_t o = qswz(row, cb);
            *(uint4*)(sm + SM_QH + o) = *(const uint4*)(qh + (size_t)row*512 + cb);
            *(uint4*)(sm + SM_QL + o) = *(const uint4*)(ql + (size_t)row*512 + cb);
        }
    }

    const char* baseKh = (const char*)&g_Khi[(size_t)(b*Nn)*Dd];
    const char* baseKl = (const char*)&g_Klo[(size_t)(b*Nn)*Dd];
    const char* baseVh = (const char*)&g_Vhi[(size_t)(b*Nn)*Dd];
    const char* baseVl = (const char*)&g_Vlo[(size_t)(b*Nn)*Dd];

    // prologue: K(0) into K stage 0  (1024 chunks per array, 512 thr -> 2 iters)
    #pragma unroll
    for (int i = 0; i < 2; i++) {
        int id = i*512 + t;
        int row = id >> 5, cb = (id & 31) * 16;
        uint32_t o = kswz(row, cb);
        CPA16(sb + SM_K + o,         baseKh + (size_t)row*512 + cb);
        CPA16(sb + SM_K + 16384 + o, baseKl + (size_t)row*512 + cb);
    }
    CPCOMMIT();

    float l0 = 0.f, l1 = 0.f;    // S-warps
    float oo[16][4];              // PV-warps: 16 rows x 128 cols
    #pragma unroll
    for (int i = 0; i < 16; i++)
        { oo[i][0] = 0.f; oo[i][1] = 0.f; oo[i][2] = 0.f; oo[i][3] = 0.f; }

    // S-warp geometry (warps 0-7): r = wid&3, cw = wid>>2
    const int sr = wid & 3, scw = (wid >> 2) & 1;
    const int key  = 16*scw + (lane >> 4)*8 + (lane & 7);
    const int kb16 = ((lane >> 3) & 1) * 16;
    // PV-warp geometry (warps 8-15): pw = (wid-8)&3, pc = (wid-8)>>2
    const int pw = (wid - 8) & 3, pc = ((wid - 8) >> 2) & 1;
    const int vr = (lane & 7) + ((lane >> 3) & 1) * 8;

    for (int j = 0; j <= 128; j++) {
        CPWAIT0();
        __syncthreads();   // K(j), V(j-1), P(j-1) visible

        // issue next-tile loads (all warps; 512 thr)
        if (j <= 126) {
            uint32_t dst = sb + SM_K + ((j+1)&1)*32768;
            size_t gb = (size_t)(j+1)*16384;
            #pragma unroll
            for (int i = 0; i < 2; i++) {
                int id = i*512 + t;
                int row = id >> 5, cb = (id & 31) * 16;
                uint32_t o = kswz(row, cb);
                CPA16(dst + o,         baseKh + gb + (size_t)row*512 + cb);
                CPA16(dst + 16384 + o, baseKl + gb + (size_t)row*512 + cb);
            }
        }
        if (j <= 127) {
            uint32_t dst = sb + SM_V + (j&1)*32768;
            size_t gb = (size_t)j*16384;
            #pragma unroll
            for (int i = 0; i < 2; i++) {
                int id = i*512 + t;
                int row = id >> 5, cb = (id & 31) * 16;
                uint32_t o = kswz(row, cb);
                CPA16(dst + o,         baseVh + gb + (size_t)row*512 + cb);
                CPA16(dst + 16384 + o, baseVl + gb + (size_t)row*512 + cb);
            }
        }
        CPCOMMIT();

        if (wid < 8) {
            // ---------------- S-group: tile j ----------------
            if (j < 128) {
                uint32_t sKh = sb + SM_K + (j&1)*32768;
                uint32_t sKl = sKh + 16384;
                const int j0 = j * 32;
                const int* mrow = mask + (size_t)(b*Nn + q0 + 16*sr + g)*Nn + j0 + 16*scw + 2*tq;
                int2 mA0 = *(const int2*)mrow;
                int2 mA1 = *(const int2*)(mrow + 8);
                int2 mB0 = *(const int2*)(mrow + 8*(size_t)Nn);
                int2 mB1 = *(const int2*)(mrow + 8*(size_t)Nn + 8);

                float s_hh[2][4] = {}, s_hl[2][4] = {}, s_lh[2][4] = {};
                #pragma unroll
                for (int ks = 0; ks < 16; ks++) {
                    uint32_t aqh[4], aql[4], bk[4], bl[4];
                    uint32_t qo = ks*32 + lk16;
                    ldsm4(aqh, sb + SM_QH + qswz(16*sr + lrow, qo));
                    ldsm4(aql, sb + SM_QL + qswz(16*sr + lrow, qo));
                    uint32_t ko = kswz(key, ks*32 + kb16);
                    ldsm4(bk, sKh + ko);
                    ldsm4(bl, sKl + ko);
                    mma16816(s_hh[0], aqh, bk);
                    mma16816(s_hl[0], aqh, bl);
                    mma16816(s_lh[0], aql, bk);
                    mma16816(s_hh[1], aqh, bk + 2);
                    mma16816(s_hl[1], aqh, bl + 2);
                    mma16816(s_lh[1], aql, bk + 2);
                }
                float sa[2][4];
                #pragma unroll
                for (int h = 0; h < 2; h++)
                    #pragma unroll
                    for (int e = 0; e < 4; e++)
                        sa[h][e] = s_hh[h][e] + s_hl[h][e] + s_lh[h][e];

                const float sc = 0.0625f;
                float p00 = mA0.x ? __expf(sa[0][0]*sc) : 0.f;
                float p01 = mA0.y ? __expf(sa[0][1]*sc) : 0.f;
                float p02 = mB0.x ? __expf(sa[0][2]*sc) : 0.f;
                float p03 = mB0.y ? __expf(sa[0][3]*sc) : 0.f;
                float p10 = mA1.x ? __expf(sa[1][0]*sc) : 0.f;
                float p11 = mA1.y ? __expf(sa[1][1]*sc) : 0.f;
                float p12 = mB1.x ? __expf(sa[1][2]*sc) : 0.f;
                float p13 = mB1.y ? __expf(sa[1][3]*sc) : 0.f;
                l0 += p00 + p01 + p10 + p11;
                l1 += p02 + p03 + p12 + p13;
                char* pb = sm + SM_P + (j&1)*8192;
                int colb = (16*scw + 2*tq) * 2;
                int row0 = 16*sr + g;
                #pragma unroll
                for (int nt = 0; nt < 2; nt++) {
                    float pa = nt ? p10 : p00, pbv = nt ? p11 : p01;
                    float pcv = nt ? p12 : p02, pd = nt ? p13 : p03;
                    uint32_t phT = __bfloat16_as_ushort(__float2bfloat16(pa))
                                 | ((uint32_t)__bfloat16_as_ushort(__float2bfloat16(pbv)) << 16);
                    uint32_t phB = __bfloat16_as_ushort(__float2bfloat16(pcv))
                                 | ((uint32_t)__bfloat16_as_ushort(__float2bfloat16(pd)) << 16);
                    int cb2 = colb + nt*16;
                    *(uint32_t*)(pb + pswz(row0,     cb2)) = phT;
                    *(uint32_t*)(pb + pswz(row0 + 8, cb2)) = phB;
                }
            } else {
                // final iter: publish row sums (K ring dead)
                float a0 = l0, a1 = l1;
                a0 += __shfl_xor_sync(0xffffffffu, a0, 1);
                a0 += __shfl_xor_sync(0xffffffffu, a0, 2);
                a1 += __shfl_xor_sync(0xffffffffu, a1, 1);
                a1 += __shfl_xor_sync(0xffffffffu, a1, 2);
                float* Ls = (float*)(sm + SM_K);
                if (tq == 0) {
                    Ls[scw*64 + 16*sr + g]     = a0;
                    Ls[scw*64 + 16*sr + 8 + g] = a1;
                }
            }
        } else if (j >= 1) {
            // ---------------- PV-group: tile j-1 ----------------
            const int i_ = j - 1;
            uint32_t sVh = sb + SM_V + (i_&1)*32768;
            uint32_t sVl = sVh + 16384;
            uint32_t pbuf = sb + SM_P + (i_&1)*8192;
            #pragma unroll
            for (int kc = 0; kc < 2; kc++) {
                uint32_t aph[4];
                ldsm4(aph, pbuf + pswz(16*pw + lrow, kc*32 + lk16));
                #pragma unroll
                for (int n2 = 0; n2 < 8; n2++) {
                    int vcb = (128*pc + n2*16 + (lane >> 4)*8) * 2;
                    uint32_t vo = kswz(kc*16 + vr, vcb);
                    uint32_t bvh[4], bvl[4];
                    ldsm4t(bvh, sVh + vo);
                    ldsm4t(bvl, sVl + vo);
                    mma16816(oo[n2*2],   aph, bvh);
                    mma16816(oo[n2*2],   aph, bvl);
                    mma16816(oo[n2*2+1], aph, bvh + 2);
                    mma16816(oo[n2*2+1], aph, bvl + 2);
                }
            }
        }
    }

    __syncthreads();   // Ls written, all PV done
    if (wid >= 8) {
        const float* Ls = (const float*)(sm + SM_K);
        float inv0 = 1.0f / (Ls[16*pw + g]     + Ls[64 + 16*pw + g]);
        float inv1 = 1.0f / (Ls[16*pw + 8 + g] + Ls[64 + 16*pw + 8 + g]);
        size_t row0 = (size_t)(b*Nn + q0 + 16*pw + g);
        #pragma unroll
        for (int n8 = 0; n8 < 16; n8++) {
            int col = 128*pc + n8*8 + 2*tq;
            *(float2*)&out[row0*Dd + col]     = make_float2(oo[n8][0]*inv0, oo[n8][1]*inv0);
            *(float2*)&out[(row0+8)*Dd + col] = make_float2(oo[n8][2]*inv1, oo[n8][3]*inv1);
        }
    }
}

extern "C" void kernel_launch(void* const* d_in, const int* in_sizes, int n_in,
                              void* d_out, int out_size)
{
    const float* x    = (const float*)d_in[0];
    const int*   mask = (const int*)  d_in[1];
    const float* Wq   = (const float*)d_in[2];
    const float* bq   = (const float*)d_in[3];
    const float* Wk   = (const float*)d_in[4];
    const float* bk   = (const float*)d_in[5];
    const float* Wv   = (const float*)d_in[6];
    const float* bv   = (const float*)d_in[7];
    float* out = (float*)d_out;

    cudaFuncSetAttribute(attn_kernel,
                         cudaFuncAttributeMaxDynamicSharedMemorySize, SM_TOT);
    cudaFuncSetAttribute(qkvmm_kernel,
                         cudaFuncAttributeMaxDynamicSharedMemorySize, SM_QKV_TOT);

    convX_kernel<<<Mm*Dd/1024, 256>>>(x);
    dim3 gW(Dd*Dd/1024, 3);
    convW_kernel<<<gW, 256>>>(Wq, Wk, Wv);
    dim3 gM(3, Mm/128);
    qkvmm_kernel<<<gM, 256, SM_QKV_TOT>>>(bq, bk, bv);
    dim3 g2(Nn/64, Bb);
    attn_kernel<<<g2, 512, SM_TOT>>>(mask, out);
}

// round 12
// speedup vs baseline: 1.1440x; 1.1440x over previous
#include <cuda_runtime.h>
#include <cuda_bf16.h>
#include <cstdint>

#define Bb 4
#define Nn 4096
#define Dd 256
#define Mm (Bb*Nn)

__device__ __nv_bfloat16 g_xhi[Mm*Dd], g_xlo[Mm*Dd];
__device__ __nv_bfloat16 g_Whi[3*Dd*Dd], g_Wlo[3*Dd*Dd];
__device__ __nv_bfloat16 g_Qhi[Mm*Dd], g_Qlo[Mm*Dd];
__device__ __nv_bfloat16 g_Khi[Mm*Dd], g_Klo[Mm*Dd];
__device__ __nv_bfloat16 g_Vhi[Mm*Dd], g_Vlo[Mm*Dd];

// ---------------- mma.sync / ldmatrix / cp.async ----------------
__device__ __forceinline__ uint32_t smem_u32(const void* p)
{ uint32_t a;
  asm("{ .reg .u64 t; cvta.to.shared.u64 t, %1; cvt.u32.u64 %0, t; }":"=r"(a):"l"(p));
  return a; }

__device__ __forceinline__ void ldsm4(uint32_t* r, uint32_t a)
{ asm volatile("ldmatrix.sync.aligned.m8n8.x4.shared.b16 {%0,%1,%2,%3}, [%4];"
    : "=r"(r[0]), "=r"(r[1]), "=r"(r[2]), "=r"(r[3]) : "r"(a)); }
__device__ __forceinline__ void ldsm4t(uint32_t* r, uint32_t a)
{ asm volatile("ldmatrix.sync.aligned.m8n8.x4.trans.shared.b16 {%0,%1,%2,%3}, [%4];"
    : "=r"(r[0]), "=r"(r[1]), "=r"(r[2]), "=r"(r[3]) : "r"(a)); }

__device__ __forceinline__ void mma16816(float* c, const uint32_t* a, const uint32_t* b)
{ asm volatile("mma.sync.aligned.m16n8k16.row.col.f32.bf16.bf16.f32 "
    "{%0,%1,%2,%3}, {%4,%5,%6,%7}, {%8,%9}, {%0,%1,%2,%3};"
    : "+f"(c[0]), "+f"(c[1]), "+f"(c[2]), "+f"(c[3])
    : "r"(a[0]), "r"(a[1]), "r"(a[2]), "r"(a[3]), "r"(b[0]), "r"(b[1])); }

#define CPA16(d, s) asm volatile("cp.async.cg.shared.global [%0], [%1], 16;"::"r"(d),"l"(s))
#define CPCOMMIT()  asm volatile("cp.async.commit_group;":::"memory")
#define CPWAIT0()   asm volatile("cp.async.wait_group 0;":::"memory")

// swizzled blocked-atom layouts (Swizzle<3,4,3>, 128B rows)
#define SWZ(o) ((o) ^ (((o) >> 3) & 0x70))
__device__ __forceinline__ uint32_t xswz(int r, int cb)   // 128 rows x 512B
{ return SWZ((uint32_t)((((r>>3) + (cb>>7)*16)*1024) + (r&7)*128 + (cb&127))); }
__device__ __forceinline__ uint32_t qswz(int r, int cb)   // 64 rows x 512B
{ return SWZ((uint32_t)((((r>>3) + (cb>>7)*8)*1024) + (r&7)*128 + (cb&127))); }
__device__ __forceinline__ uint32_t kswz(int r, int cb)   // 32 rows x 512B
{ return SWZ((uint32_t)((((r>>3) + (cb>>7)*4)*1024) + (r&7)*128 + (cb&127))); }
__device__ __forceinline__ uint32_t pswz(int r, int cb)   // 128B rows
{ return SWZ((uint32_t)(r*128 + cb)); }

// attention SMEM map
#define SM_QH 0
#define SM_QL 32768
#define SM_K  65536    // 2 stages x 32KB (Kh 16K | Kl 16K)
#define SM_V  131072   // 2 stages x 32KB (Vh 16K | Vl 16K)
#define SM_P  196608   // 2 x 8KB
#define SM_TOT 212992

// qkvmm SMEM map
#define SMX_H 0
#define SMX_L 65536
#define SMW_H 131072
#define SMW_L 163840
#define SM_QKV_TOT 196608

// ---------------------------------------------------------------------------
// convX / convW: fp32 -> bf16 hi/lo splits
// ---------------------------------------------------------------------------
__global__ __launch_bounds__(256, 4) void convX_kernel(const float* __restrict__ x)
{
    size_t i = (size_t)(blockIdx.x * 256 + threadIdx.x) * 4;
    float4 v = *(const float4*)&x[i];
    float a[4] = {v.x, v.y, v.z, v.w};
    ushort h[4], l[4];
    #pragma unroll
    for (int k = 0; k < 4; k++) {
        __nv_bfloat16 hb = __float2bfloat16(a[k]);
        h[k] = __bfloat16_as_ushort(hb);
        l[k] = __bfloat16_as_ushort(__float2bfloat16(a[k] - __bfloat162float(hb)));
    }
    *(uint2*)&g_xhi[i] = make_uint2(h[0] | ((uint32_t)h[1]<<16), h[2] | ((uint32_t)h[3]<<16));
    *(uint2*)&g_xlo[i] = make_uint2(l[0] | ((uint32_t)l[1]<<16), l[2] | ((uint32_t)l[3]<<16));
}

__global__ __launch_bounds__(256, 4)
void convW_kernel(const float* __restrict__ Wq, const float* __restrict__ Wk,
                  const float* __restrict__ Wv)
{
    const int z = blockIdx.y;
    const float* in = (z == 0) ? Wq : (z == 1) ? Wk : Wv;
    size_t base = (size_t)z * Dd * Dd;
    size_t i = (size_t)(blockIdx.x * 256 + threadIdx.x) * 4;
    float4 v = *(const float4*)&in[i];
    float a[4] = {v.x, v.y, v.z, v.w};
    ushort h[4], l[4];
    #pragma unroll
    for (int k = 0; k < 4; k++) {
        __nv_bfloat16 hb = __float2bfloat16(a[k]);
        h[k] = __bfloat16_as_ushort(hb);
        l[k] = __bfloat16_as_ushort(__float2bfloat16(a[k] - __bfloat162float(hb)));
    }
    *(uint2*)&g_Whi[base + i] = make_uint2(h[0] | ((uint32_t)h[1]<<16), h[2] | ((uint32_t)h[3]<<16));
    *(uint2*)&g_Wlo[base + i] = make_uint2(l[0] | ((uint32_t)l[1]<<16), l[2] | ((uint32_t)l[3]<<16));
}

// ---------------------------------------------------------------------------
// qkvmm: HMMA QKV projection (unchanged — known good)
// ---------------------------------------------------------------------------
__global__ __launch_bounds__(256, 1)
void qkvmm_kernel(const float* __restrict__ bq, const float* __restrict__ bk,
                  const float* __restrict__ bv)
{
    extern __shared__ char sm[];
    uint32_t sb = smem_u32(sm);
    const int t = threadIdx.x, lane = t & 31, wid = t >> 5;
    const int z = blockIdx.x;
    const int m0 = blockIdx.y * 128;
    const float* bias = (z == 0) ? bq : (z == 1) ? bk : bv;
    __nv_bfloat16* ohi = (z == 0) ? g_Qhi : (z == 1) ? g_Khi : g_Vhi;
    __nv_bfloat16* olo = (z == 0) ? g_Qlo : (z == 1) ? g_Klo : g_Vlo;
    const char* xh = (const char*)g_xhi + (size_t)m0 * 512;
    const char* xl = (const char*)g_xlo + (size_t)m0 * 512;
    const char* wh = (const char*)g_Whi + (size_t)z * 131072;
    const char* wl = (const char*)g_Wlo + (size_t)z * 131072;

    #pragma unroll
    for (int i = 0; i < 16; i++) {
        int id = i*256 + t;
        int row = id >> 5, cb = (id & 31) * 16;
        uint32_t o = xswz(row, cb);
        *(uint4*)(sm + SMX_H + o) = *(const uint4*)(xh + (size_t)row*512 + cb);
        *(uint4*)(sm + SMX_L + o) = *(const uint4*)(xl + (size_t)row*512 + cb);
    }

    const int lrow = lane & 15, lk16 = (lane >> 4) * 16;
    const int wrow = (lane >> 4) * 8 + (lane & 7);
    const int kb16 = ((lane >> 3) & 1) * 16;
    const int g = lane >> 2, tq = lane & 3;

    for (int et = 0; et < 4; et++) {
        __syncthreads();
        const char* wph = wh + (size_t)et * 64 * 512;
        const char* wpl = wl + (size_t)et * 64 * 512;
        #pragma unroll
        for (int i = 0; i < 8; i++) {
            int id = i*256 + t;
            int row = id >> 5, cb = (id & 31) * 16;
            uint32_t o = qswz(row, cb);
            *(uint4*)(sm + SMW_H + o) = *(const uint4*)(wph + (size_t)row*512 + cb);
            *(uint4*)(sm + SMW_L + o) = *(const uint4*)(wpl + (size_t)row*512 + cb);
        }
        __syncthreads();

        float acc[8][4] = {};
        #pragma unroll
        for (int ks = 0; ks < 16; ks++) {
            uint32_t axh[4], axl[4];
            uint32_t xo = xswz(16*wid + lrow, ks*32 + lk16);
            ldsm4(axh, sb + SMX_H + xo);
            ldsm4(axl, sb + SMX_L + xo);
            #pragma unroll
            for (int n16 = 0; n16 < 4; n16++) {
                uint32_t bwh[4], bwl[4];
                uint32_t wo = qswz(n16*16 + wrow, ks*32 + kb16);
                ldsm4(bwh, sb + SMW_H + wo);
                ldsm4(bwl, sb + SMW_L + wo);
                mma16816(acc[n16*2],   axh, bwh);
                mma16816(acc[n16*2],   axh, bwl);
                mma16816(acc[n16*2],   axl, bwh);
                mma16816(acc[n16*2+1], axh, bwh + 2);
                mma16816(acc[n16*2+1], axh, bwl + 2);
                mma16816(acc[n16*2+1], axl, bwh + 2);
            }
        }

        size_t row0 = (size_t)(m0 + 16*wid + g);
        #pragma unroll
        for (int n2 = 0; n2 < 8; n2++) {
            int col = et*64 + n2*8 + 2*tq;
            float b0 = bias[col], b1 = bias[col + 1];
            float v00 = acc[n2][0] + b0, v01 = acc[n2][1] + b1;
            float v10 = acc[n2][2] + b0, v11 = acc[n2][3] + b1;
            __nv_bfloat16 h00 = __float2bfloat16(v00), h01 = __float2bfloat16(v01);
            __nv_bfloat16 h10 = __float2bfloat16(v10), h11 = __float2bfloat16(v11);
            uint32_t hw0 = __bfloat16_as_ushort(h00) | ((uint32_t)__bfloat16_as_ushort(h01) << 16);
            uint32_t hw1 = __bfloat16_as_ushort(h10) | ((uint32_t)__bfloat16_as_ushort(h11) << 16);
            ushort l00 = __bfloat16_as_ushort(__float2bfloat16(v00 - __bfloat162float(h00)));
            ushort l01 = __bfloat16_as_ushort(__float2bfloat16(v01 - __bfloat162float(h01)));
            ushort l10 = __bfloat16_as_ushort(__float2bfloat16(v10 - __bfloat162float(h10)));
            ushort l11 = __bfloat16_as_ushort(__float2bfloat16(v11 - __bfloat162float(h11)));
            uint32_t lw0 = l00 | ((uint32_t)l01 << 16);
            uint32_t lw1 = l10 | ((uint32_t)l11 << 16);
            *(uint32_t*)&ohi[row0*Dd + col]       = hw0;
            *(uint32_t*)&olo[row0*Dd + col]       = lw0;
            *(uint32_t*)&ohi[(row0 + 8)*Dd + col] = hw1;
            *(uint32_t*)&olo[(row0 + 8)*Dd + col] = lw1;
        }
    }
}

// ---------------------------------------------------------------------------
// HMMA flash attention (R9 base): 256 thr, merged warps (4 row x 2 col).
// R12 change: PV(j-1) BEFORE S(j), P double-buffered, ONE sync per tile.
// ---------------------------------------------------------------------------
__global__ __launch_bounds__(256, 1)
void attn_kernel(const int* __restrict__ mask, float* __restrict__ out)
{
    extern __shared__ char sm[];
    uint32_t sb = smem_u32(sm);
    const int t = threadIdx.x, lane = t & 31, wid = t >> 5;
    const int r = wid & 3, cw = wid >> 2;
    const int b = blockIdx.y, q0 = blockIdx.x * 64;
    const int g = lane >> 2, tq = lane & 3;
    const int lrow = lane & 15, lk16 = (lane >> 4) * 16;

    // Q hi/lo -> smem (blocked swizzled)
    {
        const char* qh = (const char*)&g_Qhi[(size_t)(b*Nn + q0)*Dd];
        const char* ql = (const char*)&g_Qlo[(size_t)(b*Nn + q0)*Dd];
        #pragma unroll
        for (int i = 0; i < 8; i++) {
            int id = i*256 + t;
            int row = id >> 5, cb = (id & 31) * 16;
            uint32_t o = qswz(row, cb);
            *(uint4*)(sm + SM_QH + o) = *(const uint4*)(qh + (size_t)row*512 + cb);
            *(uint4*)(sm + SM_QL + o) = *(const uint4*)(ql + (size_t)row*512 + cb);
        }
    }

    const char* baseKh = (const char*)&g_Khi[(size_t)(b*Nn)*Dd];
    const char* baseKl = (const char*)&g_Klo[(size_t)(b*Nn)*Dd];
    const char* baseVh = (const char*)&g_Vhi[(size_t)(b*Nn)*Dd];
    const char* baseVl = (const char*)&g_Vlo[(size_t)(b*Nn)*Dd];

    // prologue: K(0) into K stage 0
    #pragma unroll
    for (int i = 0; i < 4; i++) {
        int id = i*256 + t;
        int row = id >> 5, cb = (id & 31) * 16;
        uint32_t o = kswz(row, cb);
        CPA16(sb + SM_K + o,         baseKh + (size_t)row*512 + cb);
        CPA16(sb + SM_K + 16384 + o, baseKl + (size_t)row*512 + cb);
    }
    CPCOMMIT();

    float l0 = 0.f, l1 = 0.f;
    float o[16][4];
    #pragma unroll
    for (int i = 0; i < 16; i++)
        { o[i][0] = 0.f; o[i][1] = 0.f; o[i][2] = 0.f; o[i][3] = 0.f; }

    const int key  = 16*cw + (lane >> 4)*8 + (lane & 7);
    const int kb16 = ((lane >> 3) & 1) * 16;
    const int vr   = (lane & 7) + ((lane >> 3) & 1) * 8;

    for (int j = 0; j <= 128; j++) {
        CPWAIT0();
        __syncthreads();   // K(j), V(j-1), P(j-1) visible; old buffers free

        // issue K(j+1) -> stage (j+1)&1, V(j) -> stage j&1
        if (j + 1 <= 127) {
            uint32_t dst = sb + SM_K + ((j+1)&1)*32768;
            size_t gb = (size_t)(j+1)*16384;
            #pragma unroll
            for (int i = 0; i < 4; i++) {
                int id = i*256 + t;
                int row = id >> 5, cb = (id & 31) * 16;
                uint32_t o2 = kswz(row, cb);
                CPA16(dst + o2,         baseKh + gb + (size_t)row*512 + cb);
                CPA16(dst + 16384 + o2, baseKl + gb + (size_t)row*512 + cb);
            }
        }
        if (j <= 127) {
            uint32_t dst = sb + SM_V + (j&1)*32768;
            size_t gb = (size_t)j*16384;
            #pragma unroll
            for (int i = 0; i < 4; i++) {
                int id = i*256 + t;
                int row = id >> 5, cb = (id & 31) * 16;
                uint32_t o2 = kswz(row, cb);
                CPA16(dst + o2,         baseVh + gb + (size_t)row*512 + cb);
                CPA16(dst + 16384 + o2, baseVl + gb + (size_t)row*512 + cb);
            }
        }
        CPCOMMIT();

        // mask prefetch for tile j (consumed after S MMAs, ~4000 cyc later)
        int2 mA0, mA1, mB0, mB1;
        if (j < 128) {
            const int* mrow = mask + (size_t)(b*Nn + q0 + 16*r + g)*Nn + j*32 + 16*cw + 2*tq;
            mA0 = *(const int2*)mrow;
            mA1 = *(const int2*)(mrow + 8);
            mB0 = *(const int2*)(mrow + 8*(size_t)Nn);
            mB1 = *(const int2*)(mrow + 8*(size_t)Nn + 8);
        }

        // ---- PV(j-1): O += Ph(j-1) (Vh + Vl) ----
        if (j >= 1) {
            const int i_ = j - 1;
            uint32_t sVh = sb + SM_V + (i_&1)*32768;
            uint32_t sVl = sVh + 16384;
            uint32_t pbuf = sb + SM_P + (i_&1)*8192;
            #pragma unroll
            for (int kc = 0; kc < 2; kc++) {
                uint32_t aph[4];
                ldsm4(aph, pbuf + pswz(16*r + lrow, kc*32 + lk16));
                #pragma unroll
                for (int n2 = 0; n2 < 8; n2++) {
                    int vcb = (128*cw + n2*16 + (lane >> 4)*8) * 2;
                    uint32_t vo = kswz(kc*16 + vr, vcb);
                    uint32_t bvh[4], bvl[4];
                    ldsm4t(bvh, sVh + vo);
                    ldsm4t(bvl, sVl + vo);
                    mma16816(o[n2*2],   aph, bvh);
                    mma16816(o[n2*2],   aph, bvl);
                    mma16816(o[n2*2+1], aph, bvh + 2);
                    mma16816(o[n2*2+1], aph, bvl + 2);
                }
            }
        }

        // ---- S(j) = Q K^T (3-term split), exp, P -> buf j&1 ----
        if (j < 128) {
            uint32_t sKh = sb + SM_K + (j&1)*32768;
            uint32_t sKl = sKh + 16384;
            float s_hh[2][4] = {}, s_hl[2][4] = {}, s_lh[2][4] = {};
            #pragma unroll
            for (int ks = 0; ks < 16; ks++) {
                uint32_t aqh[4], aql[4], bk[4], bl[4];
                uint32_t qo = ks*32 + lk16;
                ldsm4(aqh, sb + SM_QH + qswz(16*r + lrow, qo));
                ldsm4(aql, sb + SM_QL + qswz(16*r + lrow, qo));
                uint32_t ko = kswz(key, ks*32 + kb16);
                ldsm4(bk, sKh + ko);
                ldsm4(bl, sKl + ko);
                mma16816(s_hh[0], aqh, bk);
                mma16816(s_hl[0], aqh, bl);
                mma16816(s_lh[0], aql, bk);
                mma16816(s_hh[1], aqh, bk + 2);
                mma16816(s_hl[1], aqh, bl + 2);
                mma16816(s_lh[1], aql, bk + 2);
            }
            float sa[2][4];
            #pragma unroll
            for (int h = 0; h < 2; h++)
                #pragma unroll
                for (int e = 0; e < 4; e++)
                    sa[h][e] = s_hh[h][e] + s_hl[h][e] + s_lh[h][e];

            const float sc = 0.0625f;
            float p00 = mA0.x ? __expf(sa[0][0]*sc) : 0.f;
            float p01 = mA0.y ? __expf(sa[0][1]*sc) : 0.f;
            float p02 = mB0.x ? __expf(sa[0][2]*sc) : 0.f;
            float p03 = mB0.y ? __expf(sa[0][3]*sc) : 0.f;
            float p10 = mA1.x ? __expf(sa[1][0]*sc) : 0.f;
            float p11 = mA1.y ? __expf(sa[1][1]*sc) : 0.f;
            float p12 = mB1.x ? __expf(sa[1][2]*sc) : 0.f;
            float p13 = mB1.y ? __expf(sa[1][3]*sc) : 0.f;
            l0 += p00 + p01 + p10 + p11;
            l1 += p02 + p03 + p12 + p13;
            char* pb = sm + SM_P + (j&1)*8192;
            int colb = (16*cw + 2*tq) * 2;
            int row0 = 16*r + g;
            #pragma unroll
            for (int nt = 0; nt < 2; nt++) {
                float pa = nt ? p10 : p00, pbv = nt ? p11 : p01;
                float pcv = nt ? p12 : p02, pd = nt ? p13 : p03;
                uint32_t phT = __bfloat16_as_ushort(__float2bfloat16(pa))
                             | ((uint32_t)__bfloat16_as_ushort(__float2bfloat16(pbv)) << 16);
                uint32_t phB = __bfloat16_as_ushort(__float2bfloat16(pcv))
                             | ((uint32_t)__bfloat16_as_ushort(__float2bfloat16(pd)) << 16);
                int cb2 = colb + nt*16;
                *(uint32_t*)(pb + pswz(row0,     cb2)) = phT;
                *(uint32_t*)(pb + pswz(row0 + 8, cb2)) = phB;
            }
        }
    }

    // ---- epilogue: l reduce (quad + col-warp pair), scale, store ----
    l0 += __shfl_xor_sync(0xffffffffu, l0, 1);
    l0 += __shfl_xor_sync(0xffffffffu, l0, 2);
    l1 += __shfl_xor_sync(0xffffffffu, l1, 1);
    l1 += __shfl_xor_sync(0xffffffffu, l1, 2);
    __syncthreads();                      // all PV done; K ring dead
    float* Ls = (float*)(sm + SM_K);
    if (tq == 0) {
        Ls[cw*64 + 16*r + g]     = l0;
        Ls[cw*64 + 16*r + 8 + g] = l1;
    }
    __syncthreads();
    float inv0 = 1.0f / (Ls[16*r + g]     + Ls[64 + 16*r + g]);
    float inv1 = 1.0f / (Ls[16*r + 8 + g] + Ls[64 + 16*r + 8 + g]);
    size_t row0 = (size_t)(b*Nn + q0 + 16*r + g);
    #pragma unroll
    for (int nt = 0; nt < 16; nt++) {
        int col = 128*cw + nt*8 + 2*tq;
        *(float2*)&out[row0*Dd + col]       = make_float2(o[nt][0]*inv0, o[nt][1]*inv0);
        *(float2*)&out[(row0 + 8)*Dd + col] = make_float2(o[nt][2]*inv1, o[nt][3]*inv1);
    }
}

extern "C" void kernel_launch(void* const* d_in, const int* in_sizes, int n_in,
                              void* d_out, int out_size)
{
    const float* x    = (const float*)d_in[0];
    const int*   mask = (const int*)  d_in[1];
    const float* Wq   = (const float*)d_in[2];
    const float* bq   = (const float*)d_in[3];
    const float* Wk   = (const float*)d_in[4];
    const float* bk   = (const float*)d_in[5];
    const float* Wv   = (const float*)d_in[6];
    const float* bv   = (const float*)d_in[7];
    float* out = (float*)d_out;

    cudaFuncSetAttribute(attn_kernel,
                         cudaFuncAttributeMaxDynamicSharedMemorySize, SM_TOT);
    cudaFuncSetAttribute(qkvmm_kernel,
                         cudaFuncAttributeMaxDynamicSharedMemorySize, SM_QKV_TOT);

    convX_kernel<<<Mm*Dd/1024, 256>>>(x);
    dim3 gW(Dd*Dd/1024, 3);
    convW_kernel<<<gW, 256>>>(Wq, Wk, Wv);
    dim3 gM(3, Mm/128);
    qkvmm_kernel<<<gM, 256, SM_QKV_TOT>>>(bq, bk, bv);
    dim3 g2(Nn/64, Bb);
    attn_kernel<<<g2, 256, SM_TOT>>>(mask, out);
}

// round 13
// speedup vs baseline: 1.6918x; 1.4789x over previous
#include <cuda_runtime.h>
#include <cuda_bf16.h>
#include <cuda_fp16.h>
#include <cstdint>

#define Bb 4
#define Nn 4096
#define Dd 256
#define Mm (Bb*Nn)

__device__ __nv_bfloat16 g_xhi[Mm*Dd], g_xlo[Mm*Dd];
__device__ __nv_bfloat16 g_Whi[3*Dd*Dd], g_Wlo[3*Dd*Dd];
__device__ __half g_Q16[Mm*Dd], g_K16[Mm*Dd], g_V16[Mm*Dd];

// ---------------- mma.sync / ldmatrix / cp.async ----------------
__device__ __forceinline__ uint32_t smem_u32(const void* p)
{ uint32_t a;
  asm("{ .reg .u64 t; cvta.to.shared.u64 t, %1; cvt.u32.u64 %0, t; }":"=r"(a):"l"(p));
  return a; }

__device__ __forceinline__ void ldsm4(uint32_t* r, uint32_t a)
{ asm volatile("ldmatrix.sync.aligned.m8n8.x4.shared.b16 {%0,%1,%2,%3}, [%4];"
    : "=r"(r[0]), "=r"(r[1]), "=r"(r[2]), "=r"(r[3]) : "r"(a)); }
__device__ __forceinline__ void ldsm4t(uint32_t* r, uint32_t a)
{ asm volatile("ldmatrix.sync.aligned.m8n8.x4.trans.shared.b16 {%0,%1,%2,%3}, [%4];"
    : "=r"(r[0]), "=r"(r[1]), "=r"(r[2]), "=r"(r[3]) : "r"(a)); }

// bf16 MMA (qkvmm)
__device__ __forceinline__ void mma16816(float* c, const uint32_t* a, const uint32_t* b)
{ asm volatile("mma.sync.aligned.m16n8k16.row.col.f32.bf16.bf16.f32 "
    "{%0,%1,%2,%3}, {%4,%5,%6,%7}, {%8,%9}, {%0,%1,%2,%3};"
    : "+f"(c[0]), "+f"(c[1]), "+f"(c[2]), "+f"(c[3])
    : "r"(a[0]), "r"(a[1]), "r"(a[2]), "r"(a[3]), "r"(b[0]), "r"(b[1])); }
// fp16 MMA (attention)
__device__ __forceinline__ void mma16816h(float* c, const uint32_t* a, const uint32_t* b)
{ asm volatile("mma.sync.aligned.m16n8k16.row.col.f32.f16.f16.f32 "
    "{%0,%1,%2,%3}, {%4,%5,%6,%7}, {%8,%9}, {%0,%1,%2,%3};"
    : "+f"(c[0]), "+f"(c[1]), "+f"(c[2]), "+f"(c[3])
    : "r"(a[0]), "r"(a[1]), "r"(a[2]), "r"(a[3]), "r"(b[0]), "r"(b[1])); }

#define CPA16(d, s) asm volatile("cp.async.cg.shared.global [%0], [%1], 16;"::"r"(d),"l"(s))
#define CPCOMMIT()  asm volatile("cp.async.commit_group;":::"memory")
#define CPWAIT0()   asm volatile("cp.async.wait_group 0;":::"memory")

// swizzled blocked-atom layouts (Swizzle<3,4,3>, 128B rows)
#define SWZ(o) ((o) ^ (((o) >> 3) & 0x70))
__device__ __forceinline__ uint32_t xswz(int r, int cb)   // 128 rows x 512B
{ return SWZ((uint32_t)((((r>>3) + (cb>>7)*16)*1024) + (r&7)*128 + (cb&127))); }
__device__ __forceinline__ uint32_t qswz(int r, int cb)   // 64 rows x 512B
{ return SWZ((uint32_t)((((r>>3) + (cb>>7)*8)*1024) + (r&7)*128 + (cb&127))); }
__device__ __forceinline__ uint32_t kswz(int r, int cb)   // 32 rows x 512B
{ return SWZ((uint32_t)((((r>>3) + (cb>>7)*4)*1024) + (r&7)*128 + (cb&127))); }
__device__ __forceinline__ uint32_t pswz(int r, int cb)   // 128B rows
{ return SWZ((uint32_t)(r*128 + cb)); }

// attention SMEM map (fp16 single): Q 32K | K 2x16K | V 2x16K | P 2x8K
#define SM_Q  0
#define SM_K  32768
#define SM_V  65536
#define SM_P  98304
#define SM_TOT_A 114688

// qkvmm SMEM map
#define SMX_H 0
#define SMX_L 65536
#define SMW_H 131072
#define SMW_L 163840
#define SM_QKV_TOT 196608

// ---------------------------------------------------------------------------
// convX / convW: fp32 -> bf16 hi/lo splits (qkvmm inputs)
// ---------------------------------------------------------------------------
__global__ __launch_bounds__(256, 4) void convX_kernel(const float* __restrict__ x)
{
    size_t i = (size_t)(blockIdx.x * 256 + threadIdx.x) * 4;
    float4 v = *(const float4*)&x[i];
    float a[4] = {v.x, v.y, v.z, v.w};
    ushort h[4], l[4];
    #pragma unroll
    for (int k = 0; k < 4; k++) {
        __nv_bfloat16 hb = __float2bfloat16(a[k]);
        h[k] = __bfloat16_as_ushort(hb);
        l[k] = __bfloat16_as_ushort(__float2bfloat16(a[k] - __bfloat162float(hb)));
    }
    *(uint2*)&g_xhi[i] = make_uint2(h[0] | ((uint32_t)h[1]<<16), h[2] | ((uint32_t)h[3]<<16));
    *(uint2*)&g_xlo[i] = make_uint2(l[0] | ((uint32_t)l[1]<<16), l[2] | ((uint32_t)l[3]<<16));
}

__global__ __launch_bounds__(256, 4)
void convW_kernel(const float* __restrict__ Wq, const float* __restrict__ Wk,
                  const float* __restrict__ Wv)
{
    const int z = blockIdx.y;
    const float* in = (z == 0) ? Wq : (z == 1) ? Wk : Wv;
    size_t base = (size_t)z * Dd * Dd;
    size_t i = (size_t)(blockIdx.x * 256 + threadIdx.x) * 4;
    float4 v = *(const float4*)&in[i];
    float a[4] = {v.x, v.y, v.z, v.w};
    ushort h[4], l[4];
    #pragma unroll
    for (int k = 0; k < 4; k++) {
        __nv_bfloat16 hb = __float2bfloat16(a[k]);
        h[k] = __bfloat16_as_ushort(hb);
        l[k] = __bfloat16_as_ushort(__float2bfloat16(a[k] - __bfloat162float(hb)));
    }
    *(uint2*)&g_Whi[base + i] = make_uint2(h[0] | ((uint32_t)h[1]<<16), h[2] | ((uint32_t)h[3]<<16));
    *(uint2*)&g_Wlo[base + i] = make_uint2(l[0] | ((uint32_t)l[1]<<16), l[2] | ((uint32_t)l[3]<<16));
}

// ---------------------------------------------------------------------------
// qkvmm: HMMA QKV projection (bf16 3-term internal, fp32 accum) -> fp16 out
// ---------------------------------------------------------------------------
__global__ __launch_bounds__(256, 1)
void qkvmm_kernel(const float* __restrict__ bq, const float* __restrict__ bk,
                  const float* __restrict__ bv)
{
    extern __shared__ char sm[];
    uint32_t sb = smem_u32(sm);
    const int t = threadIdx.x, lane = t & 31, wid = t >> 5;
    const int z = blockIdx.x;
    const int m0 = blockIdx.y * 128;
    const float* bias = (z == 0) ? bq : (z == 1) ? bk : bv;
    __half* o16 = (z == 0) ? g_Q16 : (z == 1) ? g_K16 : g_V16;
    const char* xh = (const char*)g_xhi + (size_t)m0 * 512;
    const char* xl = (const char*)g_xlo + (size_t)m0 * 512;
    const char* wh = (const char*)g_Whi + (size_t)z * 131072;
    const char* wl = (const char*)g_Wlo + (size_t)z * 131072;

    #pragma unroll
    for (int i = 0; i < 16; i++) {
        int id = i*256 + t;
        int row = id >> 5, cb = (id & 31) * 16;
        uint32_t o = xswz(row, cb);
        *(uint4*)(sm + SMX_H + o) = *(const uint4*)(xh + (size_t)row*512 + cb);
        *(uint4*)(sm + SMX_L + o) = *(const uint4*)(xl + (size_t)row*512 + cb);
    }

    const int lrow = lane & 15, lk16 = (lane >> 4) * 16;
    const int wrow = (lane >> 4) * 8 + (lane & 7);
    const int kb16 = ((lane >> 3) & 1) * 16;
    const int g = lane >> 2, tq = lane & 3;

    for (int et = 0; et < 4; et++) {
        __syncthreads();
        const char* wph = wh + (size_t)et * 64 * 512;
        const char* wpl = wl + (size_t)et * 64 * 512;
        #pragma unroll
        for (int i = 0; i < 8; i++) {
            int id = i*256 + t;
            int row = id >> 5, cb = (id & 31) * 16;
            uint32_t o = qswz(row, cb);
            *(uint4*)(sm + SMW_H + o) = *(const uint4*)(wph + (size_t)row*512 + cb);
            *(uint4*)(sm + SMW_L + o) = *(const uint4*)(wpl + (size_t)row*512 + cb);
        }
        __syncthreads();

        float acc[8][4] = {};
        #pragma unroll
        for (int ks = 0; ks < 16; ks++) {
            uint32_t axh[4], axl[4];
            uint32_t xo = xswz(16*wid + lrow, ks*32 + lk16);
            ldsm4(axh, sb + SMX_H + xo);
            ldsm4(axl, sb + SMX_L + xo);
            #pragma unroll
            for (int n16 = 0; n16 < 4; n16++) {
                uint32_t bwh[4], bwl[4];
                uint32_t wo = qswz(n16*16 + wrow, ks*32 + kb16);
                ldsm4(bwh, sb + SMW_H + wo);
                ldsm4(bwl, sb + SMW_L + wo);
                mma16816(acc[n16*2],   axh, bwh);
                mma16816(acc[n16*2],   axh, bwl);
                mma16816(acc[n16*2],   axl, bwh);
                mma16816(acc[n16*2+1], axh, bwh + 2);
                mma16816(acc[n16*2+1], axh, bwl + 2);
                mma16816(acc[n16*2+1], axl, bwh + 2);
            }
        }

        size_t row0 = (size_t)(m0 + 16*wid + g);
        #pragma unroll
        for (int n2 = 0; n2 < 8; n2++) {
            int col = et*64 + n2*8 + 2*tq;
            float b0 = bias[col], b1 = bias[col + 1];
            __half h00 = __float2half_rn(acc[n2][0] + b0);
            __half h01 = __float2half_rn(acc[n2][1] + b1);
            __half h10 = __float2half_rn(acc[n2][2] + b0);
            __half h11 = __float2half_rn(acc[n2][3] + b1);
            uint32_t w0 = (uint32_t)__half_as_ushort(h00) | ((uint32_t)__half_as_ushort(h01) << 16);
            uint32_t w1 = (uint32_t)__half_as_ushort(h10) | ((uint32_t)__half_as_ushort(h11) << 16);
            *(uint32_t*)&o16[row0*Dd + col]       = w0;
            *(uint32_t*)&o16[(row0 + 8)*Dd + col] = w1;
        }
    }
}

// ---------------------------------------------------------------------------
// fp16 HMMA flash attention: 256 thr (4 row x 2 col warps), Br=64, Bc=32.
// R12 pipeline (PV(j-1) before S(j), P dbl-buffered, 1 sync/tile), fp16 single.
// ---------------------------------------------------------------------------
__global__ __launch_bounds__(256, 1)
void attn_kernel(const int* __restrict__ mask, float* __restrict__ out)
{
    extern __shared__ char sm[];
    uint32_t sb = smem_u32(sm);
    const int t = threadIdx.x, lane = t & 31, wid = t >> 5;
    const int r = wid & 3, cw = wid >> 2;
    const int b = blockIdx.y, q0 = blockIdx.x * 64;
    const int g = lane >> 2, tq = lane & 3;
    const int lrow = lane & 15, lk16 = (lane >> 4) * 16;

    // Q fp16 -> smem (blocked swizzled): 64 rows x 512B = 2048 chunks
    {
        const char* q16 = (const char*)&g_Q16[(size_t)(b*Nn + q0)*Dd];
        #pragma unroll
        for (int i = 0; i < 8; i++) {
            int id = i*256 + t;
            int row = id >> 5, cb = (id & 31) * 16;
            *(uint4*)(sm + SM_Q + qswz(row, cb)) =
                *(const uint4*)(q16 + (size_t)row*512 + cb);
        }
    }

    const char* baseK = (const char*)&g_K16[(size_t)(b*Nn)*Dd];
    const char* baseV = (const char*)&g_V16[(size_t)(b*Nn)*Dd];

    // prologue: K(0) into K stage 0 (16KB = 1024 chunks)
    #pragma unroll
    for (int i = 0; i < 4; i++) {
        int id = i*256 + t;
        int row = id >> 5, cb = (id & 31) * 16;
        CPA16(sb + SM_K + kswz(row, cb), baseK + (size_t)row*512 + cb);
    }
    CPCOMMIT();

    float l0 = 0.f, l1 = 0.f;
    float o[16][4];
    #pragma unroll
    for (int i = 0; i < 16; i++)
        { o[i][0] = 0.f; o[i][1] = 0.f; o[i][2] = 0.f; o[i][3] = 0.f; }

    const int key  = 16*cw + (lane >> 4)*8 + (lane & 7);
    const int kb16 = ((lane >> 3) & 1) * 16;
    const int vr   = (lane & 7) + ((lane >> 3) & 1) * 8;

    for (int j = 0; j <= 128; j++) {
        CPWAIT0();
        __syncthreads();   // K(j), V(j-1), P(j-1) visible; old buffers free

        // issue K(j+1) -> stage (j+1)&1, V(j) -> stage j&1
        if (j + 1 <= 127) {
            uint32_t dst = sb + SM_K + ((j+1)&1)*16384;
            size_t gb = (size_t)(j+1)*16384;
            #pragma unroll
            for (int i = 0; i < 4; i++) {
                int id = i*256 + t;
                int row = id >> 5, cb = (id & 31) * 16;
                CPA16(dst + kswz(row, cb), baseK + gb + (size_t)row*512 + cb);
            }
        }
        if (j <= 127) {
            uint32_t dst = sb + SM_V + (j&1)*16384;
            size_t gb = (size_t)j*16384;
            #pragma unroll
            for (int i = 0; i < 4; i++) {
                int id = i*256 + t;
                int row = id >> 5, cb = (id & 31) * 16;
                CPA16(dst + kswz(row, cb), baseV + gb + (size_t)row*512 + cb);
            }
        }
        CPCOMMIT();

        // mask prefetch for tile j (consumed after S MMAs)
        int2 mA0, mA1, mB0, mB1;
        if (j < 128) {
            const int* mrow = mask + (size_t)(b*Nn + q0 + 16*r + g)*Nn + j*32 + 16*cw + 2*tq;
            mA0 = *(const int2*)mrow;
            mA1 = *(const int2*)(mrow + 8);
            mB0 = *(const int2*)(mrow + 8*(size_t)Nn);
            mB1 = *(const int2*)(mrow + 8*(size_t)Nn + 8);
        }

        // ---- PV(j-1): O += P(j-1) V(j-1) ----
        if (j >= 1) {
            const int i_ = j - 1;
            uint32_t sV = sb + SM_V + (i_&1)*16384;
            uint32_t pbuf = sb + SM_P + (i_&1)*8192;
            #pragma unroll
            for (int kc = 0; kc < 2; kc++) {
                uint32_t aph[4];
                ldsm4(aph, pbuf + pswz(16*r + lrow, kc*32 + lk16));
                #pragma unroll
                for (int n2 = 0; n2 < 8; n2++) {
                    int vcb = (128*cw + n2*16 + (lane >> 4)*8) * 2;
                    uint32_t bv[4];
                    ldsm4t(bv, sV + kswz(kc*16 + vr, vcb));
                    mma16816h(o[n2*2],   aph, bv);
                    mma16816h(o[n2*2+1], aph, bv + 2);
                }
            }
        }

        // ---- S(j) = Q K^T (fp16 single), exp, P -> buf j&1 ----
        if (j < 128) {
            uint32_t sK = sb + SM_K + (j&1)*16384;
            float sa[2][4] = {};
            #pragma unroll
            for (int ks = 0; ks < 16; ks++) {
                uint32_t aq[4], bk[4];
                ldsm4(aq, sb + SM_Q + qswz(16*r + lrow, ks*32 + lk16));
                ldsm4(bk, sK + kswz(key, ks*32 + kb16));
                mma16816h(sa[0], aq, bk);
                mma16816h(sa[1], aq, bk + 2);
            }

            const float sc = 0.0625f;
            float p00 = mA0.x ? __expf(sa[0][0]*sc) : 0.f;
            float p01 = mA0.y ? __expf(sa[0][1]*sc) : 0.f;
            float p02 = mB0.x ? __expf(sa[0][2]*sc) : 0.f;
            float p03 = mB0.y ? __expf(sa[0][3]*sc) : 0.f;
            float p10 = mA1.x ? __expf(sa[1][0]*sc) : 0.f;
            float p11 = mA1.y ? __expf(sa[1][1]*sc) : 0.f;
            float p12 = mB1.x ? __expf(sa[1][2]*sc) : 0.f;
            float p13 = mB1.y ? __expf(sa[1][3]*sc) : 0.f;
            l0 += p00 + p01 + p10 + p11;
            l1 += p02 + p03 + p12 + p13;
            char* pb = sm + SM_P + (j&1)*8192;
            int colb = (16*cw + 2*tq) * 2;
            int row0 = 16*r + g;
            #pragma unroll
            for (int nt = 0; nt < 2; nt++) {
                float pa = nt ? p10 : p00, pbv = nt ? p11 : p01;
                float pcv = nt ? p12 : p02, pd = nt ? p13 : p03;
                uint32_t phT = (uint32_t)__half_as_ushort(__float2half_rn(pa))
                             | ((uint32_t)__half_as_ushort(__float2half_rn(pbv)) << 16);
                uint32_t phB = (uint32_t)__half_as_ushort(__float2half_rn(pcv))
                             | ((uint32_t)__half_as_ushort(__float2half_rn(pd)) << 16);
                int cb2 = colb + nt*16;
                *(uint32_t*)(pb + pswz(row0,     cb2)) = phT;
                *(uint32_t*)(pb + pswz(row0 + 8, cb2)) = phB;
            }
        }
    }

    // ---- epilogue: l reduce (quad + col-warp pair), scale, store ----
    l0 += __shfl_xor_sync(0xffffffffu, l0, 1);
    l0 += __shfl_xor_sync(0xffffffffu, l0, 2);
    l1 += __shfl_xor_sync(0xffffffffu, l1, 1);
    l1 += __shfl_xor_sync(0xffffffffu, l1, 2);
    __syncthreads();                      // all PV done; K ring dead
    float* Ls = (float*)(sm + SM_K);
    if (tq == 0) {
        Ls[cw*64 + 16*r + g]     = l0;
        Ls[cw*64 + 16*r + 8 + g] = l1;
    }
    __syncthreads();
    float inv0 = 1.0f / (Ls[16*r + g]     + Ls[64 + 16*r + g]);
    float inv1 = 1.0f / (Ls[16*r + 8 + g] + Ls[64 + 16*r + 8 + g]);
    size_t row0 = (size_t)(b*Nn + q0 + 16*r + g);
    #pragma unroll
    for (int nt = 0; nt < 16; nt++) {
        int col = 128*cw + nt*8 + 2*tq;
        *(float2*)&out[row0*Dd + col]       = make_float2(o[nt][0]*inv0, o[nt][1]*inv0);
        *(float2*)&out[(row0 + 8)*Dd + col] = make_float2(o[nt][2]*inv1, o[nt][3]*inv1);
    }
}

extern "C" void kernel_launch(void* const* d_in, const int* in_sizes, int n_in,
                              void* d_out, int out_size)
{
    const float* x    = (const float*)d_in[0];
    const int*   mask = (const int*)  d_in[1];
    const float* Wq   = (const float*)d_in[2];
    const float* bq   = (const float*)d_in[3];
    const float* Wk   = (const float*)d_in[4];
    const float* bk   = (const float*)d_in[5];
    const float* Wv   = (const float*)d_in[6];
    const float* bv   = (const float*)d_in[7];
    float* out = (float*)d_out;

    cudaFuncSetAttribute(attn_kernel,
                         cudaFuncAttributeMaxDynamicSharedMemorySize, SM_TOT_A);
    cudaFuncSetAttribute(qkvmm_kernel,
                         cudaFuncAttributeMaxDynamicSharedMemorySize, SM_QKV_TOT);

    convX_kernel<<<Mm*Dd/1024, 256>>>(x);
    dim3 gW(Dd*Dd/1024, 3);
    convW_kernel<<<gW, 256>>>(Wq, Wk, Wv);
    dim3 gM(3, Mm/128);
    qkvmm_kernel<<<gM, 256, SM_QKV_TOT>>>(bq, bk, bv);
    dim3 g2(Nn/64, Bb);
    attn_kernel<<<g2, 256, SM_TOT_A>>>(mask, out);
}

// round 14
// speedup vs baseline: 1.8404x; 1.0878x over previous
#include <cuda_runtime.h>
#include <cuda_bf16.h>
#include <cuda_fp16.h>
#include <cstdint>

#define Bb 4
#define Nn 4096
#define Dd 256
#define Mm (Bb*Nn)

__device__ __nv_bfloat16 g_xhi[Mm*Dd], g_xlo[Mm*Dd];
__device__ __nv_bfloat16 g_Whi[3*Dd*Dd], g_Wlo[3*Dd*Dd];
__device__ __half g_Q16[Mm*Dd], g_K16[Mm*Dd], g_V16[Mm*Dd];

// ---------------- mma.sync / ldmatrix / cp.async ----------------
__device__ __forceinline__ uint32_t smem_u32(const void* p)
{ uint32_t a;
  asm("{ .reg .u64 t; cvta.to.shared.u64 t, %1; cvt.u32.u64 %0, t; }":"=r"(a):"l"(p));
  return a; }

__device__ __forceinline__ void ldsm4(uint32_t* r, uint32_t a)
{ asm volatile("ldmatrix.sync.aligned.m8n8.x4.shared.b16 {%0,%1,%2,%3}, [%4];"
    : "=r"(r[0]), "=r"(r[1]), "=r"(r[2]), "=r"(r[3]) : "r"(a)); }
__device__ __forceinline__ void ldsm4t(uint32_t* r, uint32_t a)
{ asm volatile("ldmatrix.sync.aligned.m8n8.x4.trans.shared.b16 {%0,%1,%2,%3}, [%4];"
    : "=r"(r[0]), "=r"(r[1]), "=r"(r[2]), "=r"(r[3]) : "r"(a)); }

// bf16 MMA (qkvmm)
__device__ __forceinline__ void mma16816(float* c, const uint32_t* a, const uint32_t* b)
{ asm volatile("mma.sync.aligned.m16n8k16.row.col.f32.bf16.bf16.f32 "
    "{%0,%1,%2,%3}, {%4,%5,%6,%7}, {%8,%9}, {%0,%1,%2,%3};"
    : "+f"(c[0]), "+f"(c[1]), "+f"(c[2]), "+f"(c[3])
    : "r"(a[0]), "r"(a[1]), "r"(a[2]), "r"(a[3]), "r"(b[0]), "r"(b[1])); }
// fp16 MMA (attention)
__device__ __forceinline__ void mma16816h(float* c, const uint32_t* a, const uint32_t* b)
{ asm volatile("mma.sync.aligned.m16n8k16.row.col.f32.f16.f16.f32 "
    "{%0,%1,%2,%3}, {%4,%5,%6,%7}, {%8,%9}, {%0,%1,%2,%3};"
    : "+f"(c[0]), "+f"(c[1]), "+f"(c[2]), "+f"(c[3])
    : "r"(a[0]), "r"(a[1]), "r"(a[2]), "r"(a[3]), "r"(b[0]), "r"(b[1])); }

#define CPA16(d, s) asm volatile("cp.async.cg.shared.global [%0], [%1], 16;"::"r"(d),"l"(s))
#define CPCOMMIT()  asm volatile("cp.async.commit_group;":::"memory")
#define CPWAIT0()   asm volatile("cp.async.wait_group 0;":::"memory")

// swizzled blocked-atom layouts (Swizzle<3,4,3>, 128B rows)
#define SWZ(o) ((o) ^ (((o) >> 3) & 0x70))
__device__ __forceinline__ uint32_t xswz(int r, int cb)   // 128 rows x 512B
{ return SWZ((uint32_t)((((r>>3) + (cb>>7)*16)*1024) + (r&7)*128 + (cb&127))); }
__device__ __forceinline__ uint32_t qswz(int r, int cb)   // 64 rows x 512B
{ return SWZ((uint32_t)((((r>>3) + (cb>>7)*8)*1024) + (r&7)*128 + (cb&127))); }
__device__ __forceinline__ uint32_t kswz(int r, int cb)   // 32 rows x 512B
{ return SWZ((uint32_t)((((r>>3) + (cb>>7)*4)*1024) + (r&7)*128 + (cb&127))); }
__device__ __forceinline__ uint32_t pswz(int r, int cb)   // 128B rows
{ return SWZ((uint32_t)(r*128 + cb)); }

// attention SMEM map (fp16): Q 32K | K 2x16K | V 2x16K | P 2x8K
#define SM_Q  0
#define SM_K  32768
#define SM_V  65536
#define SM_P  98304
#define SM_TOT_A 114688

// qkvmm SMEM map
#define SMX_H 0
#define SMX_L 65536
#define SMW_H 131072
#define SMW_L 163840
#define SM_QKV_TOT 196608

// ---------------------------------------------------------------------------
// convX / convW: fp32 -> bf16 hi/lo splits (qkvmm inputs)
// ---------------------------------------------------------------------------
__global__ __launch_bounds__(256, 4) void convX_kernel(const float* __restrict__ x)
{
    size_t i = (size_t)(blockIdx.x * 256 + threadIdx.x) * 4;
    float4 v = *(const float4*)&x[i];
    float a[4] = {v.x, v.y, v.z, v.w};
    ushort h[4], l[4];
    #pragma unroll
    for (int k = 0; k < 4; k++) {
        __nv_bfloat16 hb = __float2bfloat16(a[k]);
        h[k] = __bfloat16_as_ushort(hb);
        l[k] = __bfloat16_as_ushort(__float2bfloat16(a[k] - __bfloat162float(hb)));
    }
    *(uint2*)&g_xhi[i] = make_uint2(h[0] | ((uint32_t)h[1]<<16), h[2] | ((uint32_t)h[3]<<16));
    *(uint2*)&g_xlo[i] = make_uint2(l[0] | ((uint32_t)l[1]<<16), l[2] | ((uint32_t)l[3]<<16));
}

__global__ __launch_bounds__(256, 4)
void convW_kernel(const float* __restrict__ Wq, const float* __restrict__ Wk,
                  const float* __restrict__ Wv)
{
    const int z = blockIdx.y;
    const float* in = (z == 0) ? Wq : (z == 1) ? Wk : Wv;
    size_t base = (size_t)z * Dd * Dd;
    size_t i = (size_t)(blockIdx.x * 256 + threadIdx.x) * 4;
    float4 v = *(const float4*)&in[i];
    float a[4] = {v.x, v.y, v.z, v.w};
    ushort h[4], l[4];
    #pragma unroll
    for (int k = 0; k < 4; k++) {
        __nv_bfloat16 hb = __float2bfloat16(a[k]);
        h[k] = __bfloat16_as_ushort(hb);
        l[k] = __bfloat16_as_ushort(__float2bfloat16(a[k] - __bfloat162float(hb)));
    }
    *(uint2*)&g_Whi[base + i] = make_uint2(h[0] | ((uint32_t)h[1]<<16), h[2] | ((uint32_t)h[3]<<16));
    *(uint2*)&g_Wlo[base + i] = make_uint2(l[0] | ((uint32_t)l[1]<<16), l[2] | ((uint32_t)l[3]<<16));
}

// ---------------------------------------------------------------------------
// qkvmm: HMMA QKV projection (bf16 3-term internal, fp32 accum) -> fp16 out
// ---------------------------------------------------------------------------
__global__ __launch_bounds__(256, 1)
void qkvmm_kernel(const float* __restrict__ bq, const float* __restrict__ bk,
                  const float* __restrict__ bv)
{
    extern __shared__ char sm[];
    uint32_t sb = smem_u32(sm);
    const int t = threadIdx.x, lane = t & 31, wid = t >> 5;
    const int z = blockIdx.x;
    const int m0 = blockIdx.y * 128;
    const float* bias = (z == 0) ? bq : (z == 1) ? bk : bv;
    __half* o16 = (z == 0) ? g_Q16 : (z == 1) ? g_K16 : g_V16;
    const char* xh = (const char*)g_xhi + (size_t)m0 * 512;
    const char* xl = (const char*)g_xlo + (size_t)m0 * 512;
    const char* wh = (const char*)g_Whi + (size_t)z * 131072;
    const char* wl = (const char*)g_Wlo + (size_t)z * 131072;

    #pragma unroll
    for (int i = 0; i < 16; i++) {
        int id = i*256 + t;
        int row = id >> 5, cb = (id & 31) * 16;
        uint32_t o = xswz(row, cb);
        *(uint4*)(sm + SMX_H + o) = *(const uint4*)(xh + (size_t)row*512 + cb);
        *(uint4*)(sm + SMX_L + o) = *(const uint4*)(xl + (size_t)row*512 + cb);
    }

    const int lrow = lane & 15, lk16 = (lane >> 4) * 16;
    const int wrow = (lane >> 4) * 8 + (lane & 7);
    const int kb16 = ((lane >> 3) & 1) * 16;
    const int g = lane >> 2, tq = lane & 3;

    for (int et = 0; et < 4; et++) {
        __syncthreads();
        const char* wph = wh + (size_t)et * 64 * 512;
        const char* wpl = wl + (size_t)et * 64 * 512;
        #pragma unroll
        for (int i = 0; i < 8; i++) {
            int id = i*256 + t;
            int row = id >> 5, cb = (id & 31) * 16;
            uint32_t o = qswz(row, cb);
            *(uint4*)(sm + SMW_H + o) = *(const uint4*)(wph + (size_t)row*512 + cb);
            *(uint4*)(sm + SMW_L + o) = *(const uint4*)(wpl + (size_t)row*512 + cb);
        }
        __syncthreads();

        float acc[8][4] = {};
        #pragma unroll
        for (int ks = 0; ks < 16; ks++) {
            uint32_t axh[4], axl[4];
            uint32_t xo = xswz(16*wid + lrow, ks*32 + lk16);
            ldsm4(axh, sb + SMX_H + xo);
            ldsm4(axl, sb + SMX_L + xo);
            #pragma unroll
            for (int n16 = 0; n16 < 4; n16++) {
                uint32_t bwh[4], bwl[4];
                uint32_t wo = qswz(n16*16 + wrow, ks*32 + kb16);
                ldsm4(bwh, sb + SMW_H + wo);
                ldsm4(bwl, sb + SMW_L + wo);
                mma16816(acc[n16*2],   axh, bwh);
                mma16816(acc[n16*2],   axh, bwl);
                mma16816(acc[n16*2],   axl, bwh);
                mma16816(acc[n16*2+1], axh, bwh + 2);
                mma16816(acc[n16*2+1], axh, bwl + 2);
                mma16816(acc[n16*2+1], axl, bwh + 2);
            }
        }

        size_t row0 = (size_t)(m0 + 16*wid + g);
        #pragma unroll
        for (int n2 = 0; n2 < 8; n2++) {
            int col = et*64 + n2*8 + 2*tq;
            float b0 = bias[col], b1 = bias[col + 1];
            __half h00 = __float2half_rn(acc[n2][0] + b0);
            __half h01 = __float2half_rn(acc[n2][1] + b1);
            __half h10 = __float2half_rn(acc[n2][2] + b0);
            __half h11 = __float2half_rn(acc[n2][3] + b1);
            uint32_t w0 = (uint32_t)__half_as_ushort(h00) | ((uint32_t)__half_as_ushort(h01) << 16);
            uint32_t w1 = (uint32_t)__half_as_ushort(h10) | ((uint32_t)__half_as_ushort(h11) << 16);
            *(uint32_t*)&o16[row0*Dd + col]       = w0;
            *(uint32_t*)&o16[(row0 + 8)*Dd + col] = w1;
        }
    }
}

// ---------------------------------------------------------------------------
// fp16 HMMA flash attention: R13 pipeline + persistent Q register fragments.
// ---------------------------------------------------------------------------
__global__ __launch_bounds__(256, 1)
void attn_kernel(const int* __restrict__ mask, float* __restrict__ out)
{
    extern __shared__ char sm[];
    uint32_t sb = smem_u32(sm);
    const int t = threadIdx.x, lane = t & 31, wid = t >> 5;
    const int r = wid & 3, cw = wid >> 2;
    const int b = blockIdx.y, q0 = blockIdx.x * 64;
    const int g = lane >> 2, tq = lane & 3;
    const int lrow = lane & 15, lk16 = (lane >> 4) * 16;

    // Q fp16 -> smem (blocked swizzled)
    {
        const char* q16 = (const char*)&g_Q16[(size_t)(b*Nn + q0)*Dd];
        #pragma unroll
        for (int i = 0; i < 8; i++) {
            int id = i*256 + t;
            int row = id >> 5, cb = (id & 31) * 16;
            *(uint4*)(sm + SM_Q + qswz(row, cb)) =
                *(const uint4*)(q16 + (size_t)row*512 + cb);
        }
    }

    const char* baseK = (const char*)&g_K16[(size_t)(b*Nn)*Dd];
    const char* baseV = (const char*)&g_V16[(size_t)(b*Nn)*Dd];

    // prologue: K(0) into K stage 0
    #pragma unroll
    for (int i = 0; i < 4; i++) {
        int id = i*256 + t;
        int row = id >> 5, cb = (id & 31) * 16;
        CPA16(sb + SM_K + kswz(row, cb), baseK + (size_t)row*512 + cb);
    }
    CPCOMMIT();

    __syncthreads();   // Q smem visible

    // persistent Q fragments: 16 ks x 4 regs (one-time ldsm)
    uint32_t qf[16][4];
    #pragma unroll
    for (int ks = 0; ks < 16; ks++)
        ldsm4(qf[ks], sb + SM_Q + qswz(16*r + lrow, ks*32 + lk16));

    float l0 = 0.f, l1 = 0.f;
    float o[16][4];
    #pragma unroll
    for (int i = 0; i < 16; i++)
        { o[i][0] = 0.f; o[i][1] = 0.f; o[i][2] = 0.f; o[i][3] = 0.f; }

    const int key  = 16*cw + (lane >> 4)*8 + (lane & 7);
    const int kb16 = ((lane >> 3) & 1) * 16;
    const int vr   = (lane & 7) + ((lane >> 3) & 1) * 8;

    for (int j = 0; j <= 128; j++) {
        CPWAIT0();
        __syncthreads();   // K(j), V(j-1), P(j-1) visible; old buffers free

        // issue K(j+1) -> stage (j+1)&1, V(j) -> stage j&1
        if (j + 1 <= 127) {
            uint32_t dst = sb + SM_K + ((j+1)&1)*16384;
            size_t gb = (size_t)(j+1)*16384;
            #pragma unroll
            for (int i = 0; i < 4; i++) {
                int id = i*256 + t;
                int row = id >> 5, cb = (id & 31) * 16;
                CPA16(dst + kswz(row, cb), baseK + gb + (size_t)row*512 + cb);
            }
        }
        if (j <= 127) {
            uint32_t dst = sb + SM_V + (j&1)*16384;
            size_t gb = (size_t)j*16384;
            #pragma unroll
            for (int i = 0; i < 4; i++) {
                int id = i*256 + t;
                int row = id >> 5, cb = (id & 31) * 16;
                CPA16(dst + kswz(row, cb), baseV + gb + (size_t)row*512 + cb);
            }
        }
        CPCOMMIT();

        // mask prefetch for tile j (consumed after S MMAs)
        int2 mA0, mA1, mB0, mB1;
        if (j < 128) {
            const int* mrow = mask + (size_t)(b*Nn + q0 + 16*r + g)*Nn + j*32 + 16*cw + 2*tq;
            mA0 = *(const int2*)mrow;
            mA1 = *(const int2*)(mrow + 8);
            mB0 = *(const int2*)(mrow + 8*(size_t)Nn);
            mB1 = *(const int2*)(mrow + 8*(size_t)Nn + 8);
        }

        // ---- PV(j-1): O += P(j-1) V(j-1) ----
        if (j >= 1) {
            const int i_ = j - 1;
            uint32_t sV = sb + SM_V + (i_&1)*16384;
            uint32_t pbuf = sb + SM_P + (i_&1)*8192;
            #pragma unroll
            for (int kc = 0; kc < 2; kc++) {
                uint32_t aph[4];
                ldsm4(aph, pbuf + pswz(16*r + lrow, kc*32 + lk16));
                #pragma unroll
                for (int n2 = 0; n2 < 8; n2++) {
                    int vcb = (128*cw + n2*16 + (lane >> 4)*8) * 2;
                    uint32_t bv[4];
                    ldsm4t(bv, sV + kswz(kc*16 + vr, vcb));
                    mma16816h(o[n2*2],   aph, bv);
                    mma16816h(o[n2*2+1], aph, bv + 2);
                }
            }
        }

        // ---- S(j) = Q K^T (Q from registers), exp, P -> buf j&1 ----
        if (j < 128) {
            uint32_t sK = sb + SM_K + (j&1)*16384;
            float sa[2][4] = {};
            #pragma unroll
            for (int ks = 0; ks < 16; ks++) {
                uint32_t bk[4];
                ldsm4(bk, sK + kswz(key, ks*32 + kb16));
                mma16816h(sa[0], qf[ks], bk);
                mma16816h(sa[1], qf[ks], bk + 2);
            }

            const float sc = 0.0625f;
            float p00 = mA0.x ? __expf(sa[0][0]*sc) : 0.f;
            float p01 = mA0.y ? __expf(sa[0][1]*sc) : 0.f;
            float p02 = mB0.x ? __expf(sa[0][2]*sc) : 0.f;
            float p03 = mB0.y ? __expf(sa[0][3]*sc) : 0.f;
            float p10 = mA1.x ? __expf(sa[1][0]*sc) : 0.f;
            float p11 = mA1.y ? __expf(sa[1][1]*sc) : 0.f;
            float p12 = mB1.x ? __expf(sa[1][2]*sc) : 0.f;
            float p13 = mB1.y ? __expf(sa[1][3]*sc) : 0.f;
            l0 += p00 + p01 + p10 + p11;
            l1 += p02 + p03 + p12 + p13;
            char* pb = sm + SM_P + (j&1)*8192;
            int colb = (16*cw + 2*tq) * 2;
            int row0 = 16*r + g;
            #pragma unroll
            for (int nt = 0; nt < 2; nt++) {
                float pa = nt ? p10 : p00, pbv = nt ? p11 : p01;
                float pcv = nt ? p12 : p02, pd = nt ? p13 : p03;
                uint32_t phT = (uint32_t)__half_as_ushort(__float2half_rn(pa))
                             | ((uint32_t)__half_as_ushort(__float2half_rn(pbv)) << 16);
                uint32_t phB = (uint32_t)__half_as_ushort(__float2half_rn(pcv))
                             | ((uint32_t)__half_as_ushort(__float2half_rn(pd)) << 16);
                int cb2 = colb + nt*16;
                *(uint32_t*)(pb + pswz(row0,     cb2)) = phT;
                *(uint32_t*)(pb + pswz(row0 + 8, cb2)) = phB;
            }
        }
    }

    // ---- epilogue: l reduce (quad + col-warp pair), scale, store ----
    l0 += __shfl_xor_sync(0xffffffffu, l0, 1);
    l0 += __shfl_xor_sync(0xffffffffu, l0, 2);
    l1 += __shfl_xor_sync(0xffffffffu, l1, 1);
    l1 += __shfl_xor_sync(0xffffffffu, l1, 2);
    __syncthreads();                      // all PV done; K ring dead
    float* Ls = (float*)(sm + SM_K);
    if (tq == 0) {
        Ls[cw*64 + 16*r + g]     = l0;
        Ls[cw*64 + 16*r + 8 + g] = l1;
    }
    __syncthreads();
    float inv0 = 1.0f / (Ls[16*r + g]     + Ls[64 + 16*r + g]);
    float inv1 = 1.0f / (Ls[16*r + 8 + g] + Ls[64 + 16*r + 8 + g]);
    size_t row0 = (size_t)(b*Nn + q0 + 16*r + g);
    #pragma unroll
    for (int nt = 0; nt < 16; nt++) {
        int col = 128*cw + nt*8 + 2*tq;
        *(float2*)&out[row0*Dd + col]       = make_float2(o[nt][0]*inv0, o[nt][1]*inv0);
        *(float2*)&out[(row0 + 8)*Dd + col] = make_float2(o[nt][2]*inv1, o[nt][3]*inv1);
    }
}

extern "C" void kernel_launch(void* const* d_in, const int* in_sizes, int n_in,
                              void* d_out, int out_size)
{
    const float* x    = (const float*)d_in[0];
    const int*   mask = (const int*)  d_in[1];
    const float* Wq   = (const float*)d_in[2];
    const float* bq   = (const float*)d_in[3];
    const float* Wk   = (const float*)d_in[4];
    const float* bk   = (const float*)d_in[5];
    const float* Wv   = (const float*)d_in[6];
    const float* bv   = (const float*)d_in[7];
    float* out = (float*)d_out;

    cudaFuncSetAttribute(attn_kernel,
                         cudaFuncAttributeMaxDynamicSharedMemorySize, SM_TOT_A);
    cudaFuncSetAttribute(qkvmm_kernel,
                         cudaFuncAttributeMaxDynamicSharedMemorySize, SM_QKV_TOT);

    convX_kernel<<<Mm*Dd/1024, 256>>>(x);
    dim3 gW(Dd*Dd/1024, 3);
    convW_kernel<<<gW, 256>>>(Wq, Wk, Wv);
    dim3 gM(3, Mm/128);
    qkvmm_kernel<<<gM, 256, SM_QKV_TOT>>>(bq, bk, bv);
    dim3 g2(Nn/64, Bb);
    attn_kernel<<<g2, 256, SM_TOT_A>>>(mask, out);
}

// round 15
// speedup vs baseline: 1.9381x; 1.0531x over previous
#include <cuda_runtime.h>
#include <cuda_fp16.h>
#include <cstdint>

#define Bb 4
#define Nn 4096
#define Dd 256
#define Mm (Bb*Nn)

__device__ __half g_x16[Mm*Dd];
__device__ __half g_W16[3*Dd*Dd];
__device__ __half g_Q16[Mm*Dd], g_K16[Mm*Dd], g_V16[Mm*Dd];

// ---------------- mma.sync / ldmatrix / cp.async ----------------
__device__ __forceinline__ uint32_t smem_u32(const void* p)
{ uint32_t a;
  asm("{ .reg .u64 t; cvta.to.shared.u64 t, %1; cvt.u32.u64 %0, t; }":"=r"(a):"l"(p));
  return a; }

__device__ __forceinline__ void ldsm4(uint32_t* r, uint32_t a)
{ asm volatile("ldmatrix.sync.aligned.m8n8.x4.shared.b16 {%0,%1,%2,%3}, [%4];"
    : "=r"(r[0]), "=r"(r[1]), "=r"(r[2]), "=r"(r[3]) : "r"(a)); }
__device__ __forceinline__ void ldsm4t(uint32_t* r, uint32_t a)
{ asm volatile("ldmatrix.sync.aligned.m8n8.x4.trans.shared.b16 {%0,%1,%2,%3}, [%4];"
    : "=r"(r[0]), "=r"(r[1]), "=r"(r[2]), "=r"(r[3]) : "r"(a)); }

// fp16 MMA
__device__ __forceinline__ void mma16816h(float* c, const uint32_t* a, const uint32_t* b)
{ asm volatile("mma.sync.aligned.m16n8k16.row.col.f32.f16.f16.f32 "
    "{%0,%1,%2,%3}, {%4,%5,%6,%7}, {%8,%9}, {%0,%1,%2,%3};"
    : "+f"(c[0]), "+f"(c[1]), "+f"(c[2]), "+f"(c[3])
    : "r"(a[0]), "r"(a[1]), "r"(a[2]), "r"(a[3]), "r"(b[0]), "r"(b[1])); }

#define CPA16(d, s) asm volatile("cp.async.cg.shared.global [%0], [%1], 16;"::"r"(d),"l"(s))
#define CPCOMMIT()  asm volatile("cp.async.commit_group;":::"memory")
#define CPWAIT0()   asm volatile("cp.async.wait_group 0;":::"memory")

// swizzled blocked-atom layouts (Swizzle<3,4,3>, 128B rows)
#define SWZ(o) ((o) ^ (((o) >> 3) & 0x70))
__device__ __forceinline__ uint32_t xswz(int r, int cb)   // 128 rows x 512B
{ return SWZ((uint32_t)((((r>>3) + (cb>>7)*16)*1024) + (r&7)*128 + (cb&127))); }
__device__ __forceinline__ uint32_t qswz(int r, int cb)   // 64 rows x 512B
{ return SWZ((uint32_t)((((r>>3) + (cb>>7)*8)*1024) + (r&7)*128 + (cb&127))); }
__device__ __forceinline__ uint32_t kswz(int r, int cb)   // 32 rows x 512B
{ return SWZ((uint32_t)((((r>>3) + (cb>>7)*4)*1024) + (r&7)*128 + (cb&127))); }
__device__ __forceinline__ uint32_t pswz(int r, int cb)   // 128B rows
{ return SWZ((uint32_t)(r*128 + cb)); }

// attention SMEM map (fp16): Q 32K | K 2x16K | V 2x16K | P 2x8K
#define SM_Q  0
#define SM_K  32768
#define SM_V  65536
#define SM_P  98304
#define SM_TOT_A 114688

// qkvmm SMEM map (fp16 single)
#define SMX 0
#define SMW 65536
#define SM_QKV_TOT 98304

// ---------------------------------------------------------------------------
// convX / convW: fp32 -> fp16
// ---------------------------------------------------------------------------
__global__ __launch_bounds__(256, 4) void convX_kernel(const float* __restrict__ x)
{
    size_t i = (size_t)(blockIdx.x * 256 + threadIdx.x) * 4;
    float4 v = *(const float4*)&x[i];
    uint32_t w0 = (uint32_t)__half_as_ushort(__float2half_rn(v.x))
                | ((uint32_t)__half_as_ushort(__float2half_rn(v.y)) << 16);
    uint32_t w1 = (uint32_t)__half_as_ushort(__float2half_rn(v.z))
                | ((uint32_t)__half_as_ushort(__float2half_rn(v.w)) << 16);
    *(uint2*)&g_x16[i] = make_uint2(w0, w1);
}

__global__ __launch_bounds__(256, 4)
void convW_kernel(const float* __restrict__ Wq, const float* __restrict__ Wk,
                  const float* __restrict__ Wv)
{
    const int z = blockIdx.y;
    const float* in = (z == 0) ? Wq : (z == 1) ? Wk : Wv;
    size_t base = (size_t)z * Dd * Dd;
    size_t i = (size_t)(blockIdx.x * 256 + threadIdx.x) * 4;
    float4 v = *(const float4*)&in[i];
    uint32_t w0 = (uint32_t)__half_as_ushort(__float2half_rn(v.x))
                | ((uint32_t)__half_as_ushort(__float2half_rn(v.y)) << 16);
    uint32_t w1 = (uint32_t)__half_as_ushort(__float2half_rn(v.z))
                | ((uint32_t)__half_as_ushort(__float2half_rn(v.w)) << 16);
    *(uint2*)&g_W16[base + i] = make_uint2(w0, w1);
}

// ---------------------------------------------------------------------------
// qkvmm: fp16 single-pass HMMA QKV projection (fp32 accum, bias fp32) -> fp16
// CTA = 128 m-rows x 256 e (4 e-tiles), 8 warps (warp = 16 rows x 64 e).
// ---------------------------------------------------------------------------
__global__ __launch_bounds__(256, 1)
void qkvmm_kernel(const float* __restrict__ bq, const float* __restrict__ bk,
                  const float* __restrict__ bv)
{
    extern __shared__ char sm[];
    uint32_t sb = smem_u32(sm);
    const int t = threadIdx.x, lane = t & 31, wid = t >> 5;
    const int z = blockIdx.x;
    const int m0 = blockIdx.y * 128;
    const float* bias = (z == 0) ? bq : (z == 1) ? bk : bv;
    __half* o16 = (z == 0) ? g_Q16 : (z == 1) ? g_K16 : g_V16;
    const char* xp = (const char*)g_x16 + (size_t)m0 * 512;
    const char* wp = (const char*)g_W16 + (size_t)z * 131072;

    // x tile 128 x 512B -> smem (once)
    #pragma unroll
    for (int i = 0; i < 16; i++) {
        int id = i*256 + t;           // 4096 chunks
        int row = id >> 5, cb = (id & 31) * 16;
        *(uint4*)(sm + SMX + xswz(row, cb)) = *(const uint4*)(xp + (size_t)row*512 + cb);
    }

    const int lrow = lane & 15, lk16 = (lane >> 4) * 16;
    const int wrow = (lane >> 4) * 8 + (lane & 7);
    const int kb16 = ((lane >> 3) & 1) * 16;
    const int g = lane >> 2, tq = lane & 3;

    for (int et = 0; et < 4; et++) {
        __syncthreads();
        const char* wph = wp + (size_t)et * 64 * 512;
        #pragma unroll
        for (int i = 0; i < 8; i++) {
            int id = i*256 + t;       // 2048 chunks
            int row = id >> 5, cb = (id & 31) * 16;
            *(uint4*)(sm + SMW + qswz(row, cb)) = *(const uint4*)(wph + (size_t)row*512 + cb);
        }
        __syncthreads();

        float acc[8][4] = {};
        #pragma unroll
        for (int ks = 0; ks < 16; ks++) {
            uint32_t ax[4];
            ldsm4(ax, sb + SMX + xswz(16*wid + lrow, ks*32 + lk16));
            #pragma unroll
            for (int n16 = 0; n16 < 4; n16++) {
                uint32_t bw[4];
                ldsm4(bw, sb + SMW + qswz(n16*16 + wrow, ks*32 + kb16));
                mma16816h(acc[n16*2],   ax, bw);
                mma16816h(acc[n16*2+1], ax, bw + 2);
            }
        }

        size_t row0 = (size_t)(m0 + 16*wid + g);
        #pragma unroll
        for (int n2 = 0; n2 < 8; n2++) {
            int col = et*64 + n2*8 + 2*tq;
            float b0 = bias[col], b1 = bias[col + 1];
            __half h00 = __float2half_rn(acc[n2][0] + b0);
            __half h01 = __float2half_rn(acc[n2][1] + b1);
            __half h10 = __float2half_rn(acc[n2][2] + b0);
            __half h11 = __float2half_rn(acc[n2][3] + b1);
            uint32_t w0 = (uint32_t)__half_as_ushort(h00) | ((uint32_t)__half_as_ushort(h01) << 16);
            uint32_t w1 = (uint32_t)__half_as_ushort(h10) | ((uint32_t)__half_as_ushort(h11) << 16);
            *(uint32_t*)&o16[row0*Dd + col]       = w0;
            *(uint32_t*)&o16[(row0 + 8)*Dd + col] = w1;
        }
    }
}

// ---------------------------------------------------------------------------
// fp16 HMMA flash attention (byte-identical to R14 — known good, 382 µs)
// ---------------------------------------------------------------------------
__global__ __launch_bounds__(256, 1)
void attn_kernel(const int* __restrict__ mask, float* __restrict__ out)
{
    extern __shared__ char sm[];
    uint32_t sb = smem_u32(sm);
    const int t = threadIdx.x, lane = t & 31, wid = t >> 5;
    const int r = wid & 3, cw = wid >> 2;
    const int b = blockIdx.y, q0 = blockIdx.x * 64;
    const int g = lane >> 2, tq = lane & 3;
    const int lrow = lane & 15, lk16 = (lane >> 4) * 16;

    // Q fp16 -> smem (blocked swizzled)
    {
        const char* q16 = (const char*)&g_Q16[(size_t)(b*Nn + q0)*Dd];
        #pragma unroll
        for (int i = 0; i < 8; i++) {
            int id = i*256 + t;
            int row = id >> 5, cb = (id & 31) * 16;
            *(uint4*)(sm + SM_Q + qswz(row, cb)) =
                *(const uint4*)(q16 + (size_t)row*512 + cb);
        }
    }

    const char* baseK = (const char*)&g_K16[(size_t)(b*Nn)*Dd];
    const char* baseV = (const char*)&g_V16[(size_t)(b*Nn)*Dd];

    // prologue: K(0) into K stage 0
    #pragma unroll
    for (int i = 0; i < 4; i++) {
        int id = i*256 + t;
        int row = id >> 5, cb = (id & 31) * 16;
        CPA16(sb + SM_K + kswz(row, cb), baseK + (size_t)row*512 + cb);
    }
    CPCOMMIT();

    __syncthreads();   // Q smem visible

    // persistent Q fragments: 16 ks x 4 regs (one-time ldsm)
    uint32_t qf[16][4];
    #pragma unroll
    for (int ks = 0; ks < 16; ks++)
        ldsm4(qf[ks], sb + SM_Q + qswz(16*r + lrow, ks*32 + lk16));

    float l0 = 0.f, l1 = 0.f;
    float o[16][4];
    #pragma unroll
    for (int i = 0; i < 16; i++)
        { o[i][0] = 0.f; o[i][1] = 0.f; o[i][2] = 0.f; o[i][3] = 0.f; }

    const int key  = 16*cw + (lane >> 4)*8 + (lane & 7);
    const int kb16 = ((lane >> 3) & 1) * 16;
    const int vr   = (lane & 7) + ((lane >> 3) & 1) * 8;

    for (int j = 0; j <= 128; j++) {
        CPWAIT0();
        __syncthreads();   // K(j), V(j-1), P(j-1) visible; old buffers free

        // issue K(j+1) -> stage (j+1)&1, V(j) -> stage j&1
        if (j + 1 <= 127) {
            uint32_t dst = sb + SM_K + ((j+1)&1)*16384;
            size_t gb = (size_t)(j+1)*16384;
            #pragma unroll
            for (int i = 0; i < 4; i++) {
                int id = i*256 + t;
                int row = id >> 5, cb = (id & 31) * 16;
                CPA16(dst + kswz(row, cb), baseK + gb + (size_t)row*512 + cb);
            }
        }
        if (j <= 127) {
            uint32_t dst = sb + SM_V + (j&1)*16384;
            size_t gb = (size_t)j*16384;
            #pragma unroll
            for (int i = 0; i < 4; i++) {
                int id = i*256 + t;
                int row = id >> 5, cb = (id & 31) * 16;
                CPA16(dst + kswz(row, cb), baseV + gb + (size_t)row*512 + cb);
            }
        }
        CPCOMMIT();

        // mask prefetch for tile j (consumed after S MMAs)
        int2 mA0, mA1, mB0, mB1;
        if (j < 128) {
            const int* mrow = mask + (size_t)(b*Nn + q0 + 16*r + g)*Nn + j*32 + 16*cw + 2*tq;
            mA0 = *(const int2*)mrow;
            mA1 = *(const int2*)(mrow + 8);
            mB0 = *(const int2*)(mrow + 8*(size_t)Nn);
            mB1 = *(const int2*)(mrow + 8*(size_t)Nn + 8);
        }

        // ---- PV(j-1): O += P(j-1) V(j-1) ----
        if (j >= 1) {
            const int i_ = j - 1;
            uint32_t sV = sb + SM_V + (i_&1)*16384;
            uint32_t pbuf = sb + SM_P + (i_&1)*8192;
            #pragma unroll
            for (int kc = 0; kc < 2; kc++) {
                uint32_t aph[4];
                ldsm4(aph, pbuf + pswz(16*r + lrow, kc*32 + lk16));
                #pragma unroll
                for (int n2 = 0; n2 < 8; n2++) {
                    int vcb = (128*cw + n2*16 + (lane >> 4)*8) * 2;
                    uint32_t bv[4];
                    ldsm4t(bv, sV + kswz(kc*16 + vr, vcb));
                    mma16816h(o[n2*2],   aph, bv);
                    mma16816h(o[n2*2+1], aph, bv + 2);
                }
            }
        }

        // ---- S(j) = Q K^T (Q from registers), exp, P -> buf j&1 ----
        if (j < 128) {
            uint32_t sK = sb + SM_K + (j&1)*16384;
            float sa[2][4] = {};
            #pragma unroll
            for (int ks = 0; ks < 16; ks++) {
                uint32_t bk[4];
                ldsm4(bk, sK + kswz(key, ks*32 + kb16));
                mma16816h(sa[0], qf[ks], bk);
                mma16816h(sa[1], qf[ks], bk + 2);
            }

            const float sc = 0.0625f;
            float p00 = mA0.x ? __expf(sa[0][0]*sc) : 0.f;
            float p01 = mA0.y ? __expf(sa[0][1]*sc) : 0.f;
            float p02 = mB0.x ? __expf(sa[0][2]*sc) : 0.f;
            float p03 = mB0.y ? __expf(sa[0][3]*sc) : 0.f;
            float p10 = mA1.x ? __expf(sa[1][0]*sc) : 0.f;
            float p11 = mA1.y ? __expf(sa[1][1]*sc) : 0.f;
            float p12 = mB1.x ? __expf(sa[1][2]*sc) : 0.f;
            float p13 = mB1.y ? __expf(sa[1][3]*sc) : 0.f;
            l0 += p00 + p01 + p10 + p11;
            l1 += p02 + p03 + p12 + p13;
            char* pb = sm + SM_P + (j&1)*8192;
            int colb = (16*cw + 2*tq) * 2;
            int row0 = 16*r + g;
            #pragma unroll
            for (int nt = 0; nt < 2; nt++) {
                float pa = nt ? p10 : p00, pbv = nt ? p11 : p01;
                float pcv = nt ? p12 : p02, pd = nt ? p13 : p03;
                uint32_t phT = (uint32_t)__half_as_ushort(__float2half_rn(pa))
                             | ((uint32_t)__half_as_ushort(__float2half_rn(pbv)) << 16);
                uint32_t phB = (uint32_t)__half_as_ushort(__float2half_rn(pcv))
                             | ((uint32_t)__half_as_ushort(__float2half_rn(pd)) << 16);
                int cb2 = colb + nt*16;
                *(uint32_t*)(pb + pswz(row0,     cb2)) = phT;
                *(uint32_t*)(pb + pswz(row0 + 8, cb2)) = phB;
            }
        }
    }

    // ---- epilogue: l reduce (quad + col-warp pair), scale, store ----
    l0 += __shfl_xor_sync(0xffffffffu, l0, 1);
    l0 += __shfl_xor_sync(0xffffffffu, l0, 2);
    l1 += __shfl_xor_sync(0xffffffffu, l1, 1);
    l1 += __shfl_xor_sync(0xffffffffu, l1, 2);
    __syncthreads();                      // all PV done; K ring dead
    float* Ls = (float*)(sm + SM_K);
    if (tq == 0) {
        Ls[cw*64 + 16*r + g]     = l0;
        Ls[cw*64 + 16*r + 8 + g] = l1;
    }
    __syncthreads();
    float inv0 = 1.0f / (Ls[16*r + g]     + Ls[64 + 16*r + g]);
    float inv1 = 1.0f / (Ls[16*r + 8 + g] + Ls[64 + 16*r + 8 + g]);
    size_t row0 = (size_t)(b*Nn + q0 + 16*r + g);
    #pragma unroll
    for (int nt = 0; nt < 16; nt++) {
        int col = 128*cw + nt*8 + 2*tq;
        *(float2*)&out[row0*Dd + col]       = make_float2(o[nt][0]*inv0, o[nt][1]*inv0);
        *(float2*)&out[(row0 + 8)*Dd + col] = make_float2(o[nt][2]*inv1, o[nt][3]*inv1);
    }
}

extern "C" void kernel_launch(void* const* d_in, const int* in_sizes, int n_in,
                              void* d_out, int out_size)
{
    const float* x    = (const float*)d_in[0];
    const int*   mask = (const int*)  d_in[1];
    const float* Wq   = (const float*)d_in[2];
    const float* bq   = (const float*)d_in[3];
    const float* Wk   = (const float*)d_in[4];
    const float* bk   = (const float*)d_in[5];
    const float* Wv   = (const float*)d_in[6];
    const float* bv   = (const float*)d_in[7];
    float* out = (float*)d_out;

    cudaFuncSetAttribute(attn_kernel,
                         cudaFuncAttributeMaxDynamicSharedMemorySize, SM_TOT_A);
    cudaFuncSetAttribute(qkvmm_kernel,
                         cudaFuncAttributeMaxDynamicSharedMemorySize, SM_QKV_TOT);

    convX_kernel<<<Mm*Dd/1024, 256>>>(x);
    dim3 gW(Dd*Dd/1024, 3);
    convW_kernel<<<gW, 256>>>(Wq, Wk, Wv);
    dim3 gM(3, Mm/128);
    qkvmm_kernel<<<gM, 256, SM_QKV_TOT>>>(bq, bk, bv);
    dim3 g2(Nn/64, Bb);
    attn_kernel<<<g2, 256, SM_TOT_A>>>(mask, out);
}

// round 16
// speedup vs baseline: 2.2907x; 1.1820x over previous
#include <cuda_runtime.h>
#include <cuda_fp16.h>
#include <cstdint>

#define Bb 4
#define Nn 4096
#define Dd 256
#define Mm (Bb*Nn)

__device__ __half g_x16[Mm*Dd];
__device__ __half g_W16[3*Dd*Dd];
__device__ __half g_Q16[Mm*Dd], g_K16[Mm*Dd], g_V16[Mm*Dd];

// ---------------- mma.sync / ldmatrix / cp.async ----------------
__device__ __forceinline__ uint32_t smem_u32(const void* p)
{ uint32_t a;
  asm("{ .reg .u64 t; cvta.to.shared.u64 t, %1; cvt.u32.u64 %0, t; }":"=r"(a):"l"(p));
  return a; }

__device__ __forceinline__ void ldsm4(uint32_t* r, uint32_t a)
{ asm volatile("ldmatrix.sync.aligned.m8n8.x4.shared.b16 {%0,%1,%2,%3}, [%4];"
    : "=r"(r[0]), "=r"(r[1]), "=r"(r[2]), "=r"(r[3]) : "r"(a)); }
__device__ __forceinline__ void ldsm4t(uint32_t* r, uint32_t a)
{ asm volatile("ldmatrix.sync.aligned.m8n8.x4.trans.shared.b16 {%0,%1,%2,%3}, [%4];"
    : "=r"(r[0]), "=r"(r[1]), "=r"(r[2]), "=r"(r[3]) : "r"(a)); }

// fp16 MMA
__device__ __forceinline__ void mma16816h(float* c, const uint32_t* a, const uint32_t* b)
{ asm volatile("mma.sync.aligned.m16n8k16.row.col.f32.f16.f16.f32 "
    "{%0,%1,%2,%3}, {%4,%5,%6,%7}, {%8,%9}, {%0,%1,%2,%3};"
    : "+f"(c[0]), "+f"(c[1]), "+f"(c[2]), "+f"(c[3])
    : "r"(a[0]), "r"(a[1]), "r"(a[2]), "r"(a[3]), "r"(b[0]), "r"(b[1])); }

#define CPA16(d, s) asm volatile("cp.async.cg.shared.global [%0], [%1], 16;"::"r"(d),"l"(s))
#define CPCOMMIT()  asm volatile("cp.async.commit_group;":::"memory")
#define CPWAIT0()   asm volatile("cp.async.wait_group 0;":::"memory")

// swizzled blocked-atom layouts (Swizzle<3,4,3>, 128B rows)
#define SWZ(o) ((o) ^ (((o) >> 3) & 0x70))
__device__ __forceinline__ uint32_t xswz(int r, int cb)   // 128 rows x 512B
{ return SWZ((uint32_t)((((r>>3) + (cb>>7)*16)*1024) + (r&7)*128 + (cb&127))); }
__device__ __forceinline__ uint32_t qswz(int r, int cb)   // 64 rows x 512B
{ return SWZ((uint32_t)((((r>>3) + (cb>>7)*8)*1024) + (r&7)*128 + (cb&127))); }
__device__ __forceinline__ uint32_t kswz(int r, int cb)   // 32 rows x 512B
{ return SWZ((uint32_t)((((r>>3) + (cb>>7)*4)*1024) + (r&7)*128 + (cb&127))); }
__device__ __forceinline__ uint32_t pswz(int r, int cb)   // 128B rows
{ return SWZ((uint32_t)(r*128 + cb)); }

// attention SMEM map (fp16): Q 32K | K 2x16K | V 2x16K | P 2x8K
#define SM_Q  0
#define SM_K  32768
#define SM_V  65536
#define SM_P  98304
#define SM_TOT_A 114688

// qkvmm SMEM map (fp16 single)
#define SMX 0
#define SMW 65536
#define SM_QKV_TOT 98304

// ---------------------------------------------------------------------------
// convX / convW: fp32 -> fp16
// ---------------------------------------------------------------------------
__global__ __launch_bounds__(256, 4) void convX_kernel(const float* __restrict__ x)
{
    size_t i = (size_t)(blockIdx.x * 256 + threadIdx.x) * 4;
    float4 v = *(const float4*)&x[i];
    uint32_t w0 = (uint32_t)__half_as_ushort(__float2half_rn(v.x))
                | ((uint32_t)__half_as_ushort(__float2half_rn(v.y)) << 16);
    uint32_t w1 = (uint32_t)__half_as_ushort(__float2half_rn(v.z))
                | ((uint32_t)__half_as_ushort(__float2half_rn(v.w)) << 16);
    *(uint2*)&g_x16[i] = make_uint2(w0, w1);
}

__global__ __launch_bounds__(256, 4)
void convW_kernel(const float* __restrict__ Wq, const float* __restrict__ Wk,
                  const float* __restrict__ Wv)
{
    const int z = blockIdx.y;
    const float* in = (z == 0) ? Wq : (z == 1) ? Wk : Wv;
    size_t base = (size_t)z * Dd * Dd;
    size_t i = (size_t)(blockIdx.x * 256 + threadIdx.x) * 4;
    float4 v = *(const float4*)&in[i];
    uint32_t w0 = (uint32_t)__half_as_ushort(__float2half_rn(v.x))
                | ((uint32_t)__half_as_ushort(__float2half_rn(v.y)) << 16);
    uint32_t w1 = (uint32_t)__half_as_ushort(__float2half_rn(v.z))
                | ((uint32_t)__half_as_ushort(__float2half_rn(v.w)) << 16);
    *(uint2*)&g_W16[base + i] = make_uint2(w0, w1);
}

// ---------------------------------------------------------------------------
// qkvmm: fp16 single-pass HMMA QKV projection (unchanged — known good)
// ---------------------------------------------------------------------------
__global__ __launch_bounds__(256, 1)
void qkvmm_kernel(const float* __restrict__ bq, const float* __restrict__ bk,
                  const float* __restrict__ bv)
{
    extern __shared__ char sm[];
    uint32_t sb = smem_u32(sm);
    const int t = threadIdx.x, lane = t & 31, wid = t >> 5;
    const int z = blockIdx.x;
    const int m0 = blockIdx.y * 128;
    const float* bias = (z == 0) ? bq : (z == 1) ? bk : bv;
    __half* o16 = (z == 0) ? g_Q16 : (z == 1) ? g_K16 : g_V16;
    const char* xp = (const char*)g_x16 + (size_t)m0 * 512;
    const char* wp = (const char*)g_W16 + (size_t)z * 131072;

    #pragma unroll
    for (int i = 0; i < 16; i++) {
        int id = i*256 + t;
        int row = id >> 5, cb = (id & 31) * 16;
        *(uint4*)(sm + SMX + xswz(row, cb)) = *(const uint4*)(xp + (size_t)row*512 + cb);
    }

    const int lrow = lane & 15, lk16 = (lane >> 4) * 16;
    const int wrow = (lane >> 4) * 8 + (lane & 7);
    const int kb16 = ((lane >> 3) & 1) * 16;
    const int g = lane >> 2, tq = lane & 3;

    for (int et = 0; et < 4; et++) {
        __syncthreads();
        const char* wph = wp + (size_t)et * 64 * 512;
        #pragma unroll
        for (int i = 0; i < 8; i++) {
            int id = i*256 + t;
            int row = id >> 5, cb = (id & 31) * 16;
            *(uint4*)(sm + SMW + qswz(row, cb)) = *(const uint4*)(wph + (size_t)row*512 + cb);
        }
        __syncthreads();

        float acc[8][4] = {};
        #pragma unroll
        for (int ks = 0; ks < 16; ks++) {
            uint32_t ax[4];
            ldsm4(ax, sb + SMX + xswz(16*wid + lrow, ks*32 + lk16));
            #pragma unroll
            for (int n16 = 0; n16 < 4; n16++) {
                uint32_t bw[4];
                ldsm4(bw, sb + SMW + qswz(n16*16 + wrow, ks*32 + kb16));
                mma16816h(acc[n16*2],   ax, bw);
                mma16816h(acc[n16*2+1], ax, bw + 2);
            }
        }

        size_t row0 = (size_t)(m0 + 16*wid + g);
        #pragma unroll
        for (int n2 = 0; n2 < 8; n2++) {
            int col = et*64 + n2*8 + 2*tq;
            float b0 = bias[col], b1 = bias[col + 1];
            __half h00 = __float2half_rn(acc[n2][0] + b0);
            __half h01 = __float2half_rn(acc[n2][1] + b1);
            __half h10 = __float2half_rn(acc[n2][2] + b0);
            __half h11 = __float2half_rn(acc[n2][3] + b1);
            uint32_t w0 = (uint32_t)__half_as_ushort(h00) | ((uint32_t)__half_as_ushort(h01) << 16);
            uint32_t w1 = (uint32_t)__half_as_ushort(h10) | ((uint32_t)__half_as_ushort(h11) << 16);
            *(uint32_t*)&o16[row0*Dd + col]       = w0;
            *(uint32_t*)&o16[(row0 + 8)*Dd + col] = w1;
        }
    }
}

// ---------------------------------------------------------------------------
// fp16 HMMA flash attention: R15 base + MMA-level S/PV interleave and
// 4-way split S accumulator chains.
// ---------------------------------------------------------------------------
__global__ __launch_bounds__(256, 1)
void attn_kernel(const int* __restrict__ mask, float* __restrict__ out)
{
    extern __shared__ char sm[];
    uint32_t sb = smem_u32(sm);
    const int t = threadIdx.x, lane = t & 31, wid = t >> 5;
    const int r = wid & 3, cw = wid >> 2;
    const int b = blockIdx.y, q0 = blockIdx.x * 64;
    const int g = lane >> 2, tq = lane & 3;
    const int lrow = lane & 15, lk16 = (lane >> 4) * 16;

    // Q fp16 -> smem (blocked swizzled)
    {
        const char* q16 = (const char*)&g_Q16[(size_t)(b*Nn + q0)*Dd];
        #pragma unroll
        for (int i = 0; i < 8; i++) {
            int id = i*256 + t;
            int row = id >> 5, cb = (id & 31) * 16;
            *(uint4*)(sm + SM_Q + qswz(row, cb)) =
                *(const uint4*)(q16 + (size_t)row*512 + cb);
        }
    }

    const char* baseK = (const char*)&g_K16[(size_t)(b*Nn)*Dd];
    const char* baseV = (const char*)&g_V16[(size_t)(b*Nn)*Dd];

    // prologue: K(0) into K stage 0
    #pragma unroll
    for (int i = 0; i < 4; i++) {
        int id = i*256 + t;
        int row = id >> 5, cb = (id & 31) * 16;
        CPA16(sb + SM_K + kswz(row, cb), baseK + (size_t)row*512 + cb);
    }
    CPCOMMIT();

    __syncthreads();   // Q smem visible

    // persistent Q fragments
    uint32_t qf[16][4];
    #pragma unroll
    for (int ks = 0; ks < 16; ks++)
        ldsm4(qf[ks], sb + SM_Q + qswz(16*r + lrow, ks*32 + lk16));

    float l0 = 0.f, l1 = 0.f;
    float o[16][4];
    #pragma unroll
    for (int i = 0; i < 16; i++)
        { o[i][0] = 0.f; o[i][1] = 0.f; o[i][2] = 0.f; o[i][3] = 0.f; }

    const int key  = 16*cw + (lane >> 4)*8 + (lane & 7);
    const int kb16 = ((lane >> 3) & 1) * 16;
    const int vr   = (lane & 7) + ((lane >> 3) & 1) * 8;

    for (int j = 0; j <= 128; j++) {
        CPWAIT0();
        __syncthreads();   // K(j), V(j-1), P(j-1) visible; old buffers free

        // issue K(j+1) -> stage (j+1)&1, V(j) -> stage j&1
        if (j + 1 <= 127) {
            uint32_t dst = sb + SM_K + ((j+1)&1)*16384;
            size_t gb = (size_t)(j+1)*16384;
            #pragma unroll
            for (int i = 0; i < 4; i++) {
                int id = i*256 + t;
                int row = id >> 5, cb = (id & 31) * 16;
                CPA16(dst + kswz(row, cb), baseK + gb + (size_t)row*512 + cb);
            }
        }
        if (j <= 127) {
            uint32_t dst = sb + SM_V + (j&1)*16384;
            size_t gb = (size_t)j*16384;
            #pragma unroll
            for (int i = 0; i < 4; i++) {
                int id = i*256 + t;
                int row = id >> 5, cb = (id & 31) * 16;
                CPA16(dst + kswz(row, cb), baseV + gb + (size_t)row*512 + cb);
            }
        }
        CPCOMMIT();

        // mask prefetch for tile j
        int2 mA0, mA1, mB0, mB1;
        if (j < 128) {
            const int* mrow = mask + (size_t)(b*Nn + q0 + 16*r + g)*Nn + j*32 + 16*cw + 2*tq;
            mA0 = *(const int2*)mrow;
            mA1 = *(const int2*)(mrow + 8);
            mB0 = *(const int2*)(mrow + 8*(size_t)Nn);
            mB1 = *(const int2*)(mrow + 8*(size_t)Nn + 8);
        }

        float sA[4] = {}, sB[4] = {}, sC[4] = {}, sD[4] = {};

        if (j >= 1 && j < 128) {
            // ---- fused: S(j) interleaved with PV(j-1) at MMA granularity ----
            uint32_t sK = sb + SM_K + (j&1)*16384;
            uint32_t sV = sb + SM_V + ((j-1)&1)*16384;
            uint32_t pbuf = sb + SM_P + ((j-1)&1)*8192;
            uint32_t aph[4];
            #pragma unroll
            for (int ks = 0; ks < 16; ks++) {
                uint32_t bk[4];
                ldsm4(bk, sK + kswz(key, ks*32 + kb16));
                if (ks & 1) { mma16816h(sC, qf[ks], bk); mma16816h(sD, qf[ks], bk + 2); }
                else        { mma16816h(sA, qf[ks], bk); mma16816h(sB, qf[ks], bk + 2); }
                const int kc = ks >> 3, n2 = ks & 7;
                if (n2 == 0)
                    ldsm4(aph, pbuf + pswz(16*r + lrow, kc*32 + lk16));
                int vcb = (128*cw + n2*16 + (lane >> 4)*8) * 2;
                uint32_t bv[4];
                ldsm4t(bv, sV + kswz(kc*16 + vr, vcb));
                mma16816h(o[n2*2],   aph, bv);
                mma16816h(o[n2*2+1], aph, bv + 2);
            }
        } else if (j == 0) {
            // ---- S only ----
            uint32_t sK = sb + SM_K;
            #pragma unroll
            for (int ks = 0; ks < 16; ks++) {
                uint32_t bk[4];
                ldsm4(bk, sK + kswz(key, ks*32 + kb16));
                if (ks & 1) { mma16816h(sC, qf[ks], bk); mma16816h(sD, qf[ks], bk + 2); }
                else        { mma16816h(sA, qf[ks], bk); mma16816h(sB, qf[ks], bk + 2); }
            }
        } else {
            // ---- j == 128: PV only (tile 127) ----
            uint32_t sV = sb + SM_V + (127&1)*16384;
            uint32_t pbuf = sb + SM_P + (127&1)*8192;
            #pragma unroll
            for (int kc = 0; kc < 2; kc++) {
                uint32_t aph[4];
                ldsm4(aph, pbuf + pswz(16*r + lrow, kc*32 + lk16));
                #pragma unroll
                for (int n2 = 0; n2 < 8; n2++) {
                    int vcb = (128*cw + n2*16 + (lane >> 4)*8) * 2;
                    uint32_t bv[4];
                    ldsm4t(bv, sV + kswz(kc*16 + vr, vcb));
                    mma16816h(o[n2*2],   aph, bv);
                    mma16816h(o[n2*2+1], aph, bv + 2);
                }
            }
        }

        // ---- softmax + P store (tiles 0..127) ----
        if (j < 128) {
            const float sc = 0.0625f;
            float p00 = mA0.x ? __expf((sA[0]+sC[0])*sc) : 0.f;
            float p01 = mA0.y ? __expf((sA[1]+sC[1])*sc) : 0.f;
            float p02 = mB0.x ? __expf((sA[2]+sC[2])*sc) : 0.f;
            float p03 = mB0.y ? __expf((sA[3]+sC[3])*sc) : 0.f;
            float p10 = mA1.x ? __expf((sB[0]+sD[0])*sc) : 0.f;
            float p11 = mA1.y ? __expf((sB[1]+sD[1])*sc) : 0.f;
            float p12 = mB1.x ? __expf((sB[2]+sD[2])*sc) : 0.f;
            float p13 = mB1.y ? __expf((sB[3]+sD[3])*sc) : 0.f;
            l0 += p00 + p01 + p10 + p11;
            l1 += p02 + p03 + p12 + p13;
            char* pb = sm + SM_P + (j&1)*8192;
            int colb = (16*cw + 2*tq) * 2;
            int row0 = 16*r + g;
            #pragma unroll
            for (int nt = 0; nt < 2; nt++) {
                float pa = nt ? p10 : p00, pbv = nt ? p11 : p01;
                float pcv = nt ? p12 : p02, pd = nt ? p13 : p03;
                uint32_t phT = (uint32_t)__half_as_ushort(__float2half_rn(pa))
                             | ((uint32_t)__half_as_ushort(__float2half_rn(pbv)) << 16);
                uint32_t phB = (uint32_t)__half_as_ushort(__float2half_rn(pcv))
                             | ((uint32_t)__half_as_ushort(__float2half_rn(pd)) << 16);
                int cb2 = colb + nt*16;
                *(uint32_t*)(pb + pswz(row0,     cb2)) = phT;
                *(uint32_t*)(pb + pswz(row0 + 8, cb2)) = phB;
            }
        }
    }

    // ---- epilogue: l reduce (quad + col-warp pair), scale, store ----
    l0 += __shfl_xor_sync(0xffffffffu, l0, 1);
    l0 += __shfl_xor_sync(0xffffffffu, l0, 2);
    l1 += __shfl_xor_sync(0xffffffffu, l1, 1);
    l1 += __shfl_xor_sync(0xffffffffu, l1, 2);
    __syncthreads();                      // all PV done; K ring dead
    float* Ls = (float*)(sm + SM_K);
    if (tq == 0) {
        Ls[cw*64 + 16*r + g]     = l0;
        Ls[cw*64 + 16*r + 8 + g] = l1;
    }
    __syncthreads();
    float inv0 = 1.0f / (Ls[16*r + g]     + Ls[64 + 16*r + g]);
    float inv1 = 1.0f / (Ls[16*r + 8 + g] + Ls[64 + 16*r + 8 + g]);
    size_t row0 = (size_t)(b*Nn + q0 + 16*r + g);
    #pragma unroll
    for (int nt = 0; nt < 16; nt++) {
        int col = 128*cw + nt*8 + 2*tq;
        *(float2*)&out[row0*Dd + col]       = make_float2(o[nt][0]*inv0, o[nt][1]*inv0);
        *(float2*)&out[(row0 + 8)*Dd + col] = make_float2(o[nt][2]*inv1, o[nt][3]*inv1);
    }
}

extern "C" void kernel_launch(void* const* d_in, const int* in_sizes, int n_in,
                              void* d_out, int out_size)
{
    const float* x    = (const float*)d_in[0];
    const int*   mask = (const int*)  d_in[1];
    const float* Wq   = (const float*)d_in[2];
    const float* bq   = (const float*)d_in[3];
    const float* Wk   = (const float*)d_in[4];
    const float* bk   = (const float*)d_in[5];
    const float* Wv   = (const float*)d_in[6];
    const float* bv   = (const float*)d_in[7];
    float* out = (float*)d_out;

    cudaFuncSetAttribute(attn_kernel,
                         cudaFuncAttributeMaxDynamicSharedMemorySize, SM_TOT_A);
    cudaFuncSetAttribute(qkvmm_kernel,
                         cudaFuncAttributeMaxDynamicSharedMemorySize, SM_QKV_TOT);

    convX_kernel<<<Mm*Dd/1024, 256>>>(x);
    dim3 gW(Dd*Dd/1024, 3);
    convW_kernel<<<gW, 256>>>(Wq, Wk, Wv);
    dim3 gM(3, Mm/128);
    qkvmm_kernel<<<gM, 256, SM_QKV_TOT>>>(bq, bk, bv);
    dim3 g2(Nn/64, Bb);
    attn_kernel<<<g2, 256, SM_TOT_A>>>(mask, out);
}